// round 7
// baseline (speedup 1.0000x reference)
#include <cuda_runtime.h>
#include <math.h>
#include <float.h>

#define B_    512
#define T_    247
#define C_    64
#define NTF_  200
#define LPOOL 254
#define MROWS (B_*T_)      // 126464

typedef unsigned long long u64;

// ---------------- scratch ----------------
__device__ float g_pooled[B_*C_*LPOOL];
__device__ float g_xlstm [MROWS*C_];
__device__ float g_xproj [(size_t)MROWS*512];
__device__ float g_values[MROWS*128];
__device__ float g_hT    [2*B_*64];
__device__ float g_query [B_*128];
__device__ float g_E     [MROWS*128];
__device__ float g_score [MROWS*NTF_];
__device__ float g_ctx   [B_*NTF_*128];
__device__ float g_W1T [128*128];
__device__ float g_W2T [128*128];
__device__ float g_VT  [128*NTF_];
__device__ float g_WIHT[64*512];
__device__ float g_biasIH[512];
__device__ float g_c1wT[512*64];

__device__ __forceinline__ float sigf(float x){ return 1.f/(1.f+__expf(-x)); }

// ---- packed fp32x2 helpers (FFMA2) ----
__device__ __forceinline__ u64 ffma2(u64 a, u64 b, u64 c){
    u64 d;
    asm("fma.rn.f32x2 %0, %1, %2, %3;" : "=l"(d) : "l"(a), "l"(b), "l"(c));
    return d;
}
__device__ __forceinline__ u64 pack2(float x, float y){
    u64 d;
    asm("mov.b64 %0, {%1, %2};" : "=l"(d) : "f"(x), "f"(y));
    return d;
}
__device__ __forceinline__ float2 unpack2(u64 d){
    float2 f;
    asm("mov.b64 {%0, %1}, %2;" : "=f"(f.x), "=f"(f.y) : "l"(d));
    return f;
}

// ---------------- prep ----------------
__global__ void k_prep(const float* __restrict__ W1, const float* __restrict__ W2,
                       const float* __restrict__ V,
                       const float* __restrict__ wih_f, const float* __restrict__ wih_b,
                       const float* __restrict__ bih_f, const float* __restrict__ bhh_f,
                       const float* __restrict__ bih_b, const float* __restrict__ bhh_b,
                       const float* __restrict__ c1w)
{
    int idx = blockIdx.x*blockDim.x + threadIdx.x;
    if (idx < 16384){ int n = idx/128, k = idx%128; g_W1T[k*128+n] = W1[idx]; }
    if (idx < 16384){ int n = idx/128, k = idx%128; g_W2T[k*128+n] = W2[idx]; }
    if (idx < 128*NTF_){ int n = idx/128, k = idx%128; g_VT[k*NTF_+n] = V[idx]; }
    if (idx < 16384){ int g = idx/64, k = idx%64;
        g_WIHT[k*512 + g]       = wih_f[idx];
        g_WIHT[k*512 + 256 + g] = wih_b[idx]; }
    if (idx < 512){ g_biasIH[idx] = (idx < 256) ? (bih_f[idx] + bhh_f[idx])
                                                : (bih_b[idx-256] + bhh_b[idx-256]); }
    if (idx < 32768){ int c = idx/512, k = idx%512; g_c1wT[k*64+c] = c1w[idx]; }
}

// ---------------- conv0 + bn + relu + maxpool4 ----------------
__global__ void __launch_bounds__(256) k_conv0(
    const float* __restrict__ x, const float* __restrict__ w, const float* __restrict__ cb,
    const float* __restrict__ g, const float* __restrict__ bb,
    const float* __restrict__ mm, const float* __restrict__ vv)
{
    __shared__ float4 xs4[1024];
    int b = blockIdx.x, tid = threadIdx.x;
    const float4* in4 = (const float4*)(x + (size_t)b*4096);
    for (int i = tid; i < 1024; i += 256) xs4[i] = in4[i];

    int c = tid & 63;
    float4 wr[8];
    #pragma unroll
    for (int kk = 0; kk < 8; kk++)
        wr[kk] = make_float4(w[c*32 + 0*8 + kk], w[c*32 + 1*8 + kk],
                             w[c*32 + 2*8 + kk], w[c*32 + 3*8 + kk]);
    float scale = g[c] * rsqrtf(vv[c] + 1e-5f);
    float shift = bb[c] - mm[c]*scale;
    float cbc   = cb[c];
    __syncthreads();

    for (int idx = tid; idx < 64*LPOOL; idx += 256){
        int q = idx >> 6;
        float best = -FLT_MAX;
        #pragma unroll
        for (int dp = 0; dp < 4; dp++){
            int p = 4*q + dp;
            float acc = cbc;
            #pragma unroll
            for (int kk = 0; kk < 8; kk++){
                float4 xv = xs4[p+kk];
                acc += wr[kk].x*xv.x + wr[kk].y*xv.y + wr[kk].z*xv.z + wr[kk].w*xv.w;
            }
            best = fmaxf(best, acc*scale + shift);
        }
        g_pooled[(b*64 + c)*LPOOL + q] = fmaxf(best, 0.f);
    }
}

// ---------------- f32x2 compute: A pre-duplicated u64, conflict-free B ----------------
__device__ __forceinline__ void gcomp(const u64 (&As)[16][130], const u64 (&Bs)[16][4][20],
                                      u64 (&acc)[8][4], int ty, int tx)
{
    #pragma unroll
    for (int k = 0; k < 16; k++){
        ulonglong2 a01 = *(const ulonglong2*)&As[k][ty*8+0];
        ulonglong2 a23 = *(const ulonglong2*)&As[k][ty*8+2];
        ulonglong2 a45 = *(const ulonglong2*)&As[k][ty*8+4];
        ulonglong2 a67 = *(const ulonglong2*)&As[k][ty*8+6];
        u64 b0 = Bs[k][0][tx];
        u64 b1 = Bs[k][1][tx];
        u64 b2 = Bs[k][2][tx];
        u64 b3 = Bs[k][3][tx];
        u64 av[8] = {a01.x,a01.y,a23.x,a23.y,a45.x,a45.y,a67.x,a67.y};
        #pragma unroll
        for (int i = 0; i < 8; i++){
            acc[i][0] = ffma2(av[i], b0, acc[i][0]);
            acc[i][1] = ffma2(av[i], b1, acc[i][1]);
            acc[i][2] = ffma2(av[i], b2, acc[i][2]);
            acc[i][3] = ffma2(av[i], b3, acc[i][3]);
        }
    }
}

// store one B value into the pair layout: column n (0..127), row k
__device__ __forceinline__ void bstore(u64 (&Bs)[16][4][20], int k, int n, float v){
    ((float*)&Bs[k][(n>>1)&3][n>>3])[n&1] = v;
}

// ---------------- conv1 GEMM: M=126464, N=64, K=512 (pipelined) ----------------
__global__ void __launch_bounds__(256,2) k_conv1(
    const float* __restrict__ cb,
    const float* __restrict__ gg, const float* __restrict__ bb,
    const float* __restrict__ mm, const float* __restrict__ vv)
{
    __shared__ u64 As[2][16][130];
    __shared__ u64 Bs[2][16][2][20];
    int tid = threadIdx.x;
    int m0  = blockIdx.x*128;
    int ty = tid/16, tx = tid%16;
    u64 acc[8][2];
    #pragma unroll
    for (int i=0;i<8;i++){ acc[i][0]=0ull; acc[i][1]=0ull; }

    int bzl[8], tl[8];
    #pragma unroll
    for (int r = 0; r < 8; r++){
        int i = tid + 256*r;
        int gm = m0 + (i >> 4);
        bzl[r] = gm / T_;
        tl[r]  = gm - bzl[r]*T_;
    }

    float ra[8], rb[4];
    #pragma unroll
    for (int r = 0; r < 8; r++){
        int i = tid + 256*r; int kg = i & 15;
        ra[r] = g_pooled[(bzl[r]*64 + (kg>>3))*LPOOL + tl[r] + (kg&7)];
    }
    #pragma unroll
    for (int r = 0; r < 4; r++){
        int i = tid + 256*r;
        rb[r] = g_c1wT[(i>>6)*64 + (i&63)];
    }
    #pragma unroll
    for (int r = 0; r < 8; r++){ int i = tid + 256*r; As[0][i&15][i>>4] = pack2(ra[r], ra[r]); }
    #pragma unroll
    for (int r = 0; r < 4; r++){
        int i = tid + 256*r; int n = i & 63, k = i >> 6;
        ((float*)&Bs[0][k][(n>>1)&1][n>>2])[n&1] = rb[r];
    }
    __syncthreads();

    for (int c = 0; c < 32; c++){
        if (c < 31){
            int k0 = (c+1)*16;
            #pragma unroll
            for (int r = 0; r < 8; r++){
                int i = tid + 256*r; int kg = k0 + (i & 15);
                ra[r] = g_pooled[(bzl[r]*64 + (kg>>3))*LPOOL + tl[r] + (kg&7)];
            }
            #pragma unroll
            for (int r = 0; r < 4; r++){
                int i = tid + 256*r;
                rb[r] = g_c1wT[(k0 + (i>>6))*64 + (i&63)];
            }
        }
        {
            const u64 (&A)[16][130] = As[c&1];
            const u64 (&Bv)[16][2][20] = Bs[c&1];
            #pragma unroll
            for (int k = 0; k < 16; k++){
                ulonglong2 a01 = *(const ulonglong2*)&A[k][ty*8+0];
                ulonglong2 a23 = *(const ulonglong2*)&A[k][ty*8+2];
                ulonglong2 a45 = *(const ulonglong2*)&A[k][ty*8+4];
                ulonglong2 a67 = *(const ulonglong2*)&A[k][ty*8+6];
                u64 b0 = Bv[k][0][tx];
                u64 b1 = Bv[k][1][tx];
                u64 av[8] = {a01.x,a01.y,a23.x,a23.y,a45.x,a45.y,a67.x,a67.y};
                #pragma unroll
                for (int i = 0; i < 8; i++){
                    acc[i][0] = ffma2(av[i], b0, acc[i][0]);
                    acc[i][1] = ffma2(av[i], b1, acc[i][1]);
                }
            }
        }
        if (c < 31){
            int nb = (c+1)&1;
            #pragma unroll
            for (int r = 0; r < 8; r++){ int i = tid + 256*r; As[nb][i&15][i>>4] = pack2(ra[r], ra[r]); }
            #pragma unroll
            for (int r = 0; r < 4; r++){
                int i = tid + 256*r; int n = i & 63, k = i >> 6;
                ((float*)&Bs[nb][k][(n>>1)&1][n>>2])[n&1] = rb[r];
            }
        }
        __syncthreads();
    }
    #pragma unroll
    for (int j2 = 0; j2 < 2; j2++){
        #pragma unroll
        for (int h = 0; h < 2; h++){
            int c = tx*4 + j2*2 + h;
            float scale = gg[c] * rsqrtf(vv[c] + 1e-5f);
            float shift = bb[c] + (cb[c] - mm[c])*scale;
            #pragma unroll
            for (int i = 0; i < 8; i++){
                int m = m0 + ty*8 + i;
                float2 f = unpack2(acc[i][j2]);
                float v = h ? f.y : f.x;
                g_xlstm[(size_t)m*64 + c] = fmaxf(v*scale + shift, 0.f);
            }
        }
    }
}

// ---------------- xproj GEMM: M=126464, N=512, K=64 (pipelined) ----------------
__global__ void __launch_bounds__(256,2) k_xproj()
{
    __shared__ u64 As[2][16][130];
    __shared__ u64 Bs[2][16][4][20];
    int tid = threadIdx.x;
    int n0 = blockIdx.x*128, m0 = blockIdx.y*128;
    int ty = tid/16, tx = tid%16;
    u64 acc[8][4];
    #pragma unroll
    for (int i=0;i<8;i++) for (int j=0;j<4;j++) acc[i][j]=0ull;

    float ra[8], rb[8];
    #pragma unroll
    for (int r = 0; r < 8; r++){
        int i = tid + 256*r;
        ra[r] = g_xlstm[(size_t)(m0+(i>>4))*64 + (i&15)];
        rb[r] = g_WIHT[(i>>7)*512 + n0 + (i&127)];
    }
    #pragma unroll
    for (int r = 0; r < 8; r++){
        int i = tid + 256*r;
        As[0][i&15][i>>4] = pack2(ra[r], ra[r]);
        bstore(Bs[0], i>>7, i&127, rb[r]);
    }
    __syncthreads();

    #pragma unroll
    for (int c = 0; c < 4; c++){
        if (c < 3){
            int k0 = (c+1)*16;
            #pragma unroll
            for (int r = 0; r < 8; r++){
                int i = tid + 256*r;
                ra[r] = g_xlstm[(size_t)(m0+(i>>4))*64 + k0 + (i&15)];
                rb[r] = g_WIHT[(k0+(i>>7))*512 + n0 + (i&127)];
            }
        }
        gcomp(As[c&1], Bs[c&1], acc, ty, tx);
        if (c < 3){
            int nb = (c+1)&1;
            #pragma unroll
            for (int r = 0; r < 8; r++){
                int i = tid + 256*r;
                As[nb][i&15][i>>4] = pack2(ra[r], ra[r]);
                bstore(Bs[nb], i>>7, i&127, rb[r]);
            }
        }
        __syncthreads();
    }
    #pragma unroll
    for (int i = 0; i < 8; i++){
        int m = m0 + ty*8 + i;
        #pragma unroll
        for (int j2 = 0; j2 < 4; j2++){
            float2 f = unpack2(acc[i][j2]);
            int n = n0 + tx*8 + j2*2;
            g_xproj[(size_t)m*512 + n]     = f.x + g_biasIH[n];
            g_xproj[(size_t)m*512 + n + 1] = f.y + g_biasIH[n+1];
        }
    }
}

// ---------------- LSTM recurrence (persistent, pre-packed W, 4 batches/block) ----------------
__global__ void __launch_bounds__(256,1) k_lstm(const float* __restrict__ whh_f,
                                                const float* __restrict__ whh_b)
{
    __shared__ float hs[64][4];
    __shared__ float g_sm[4][256];
    int dir = blockIdx.x >> 7;
    int b0  = (blockIdx.x & 127) * 4;
    int tid = threadIdx.x;
    const float* whh = dir ? whh_b : whh_f;

    // pre-packed duplicated weights: 64 u64 = 128 regs, hoisted out of the time loop
    u64 wpk[64];
    #pragma unroll
    for (int j = 0; j < 64; j++){
        float w = whh[tid*64 + j];
        wpk[j] = pack2(w, w);
    }

    hs[tid>>2][tid&3] = 0.f;
    float c = 0.f, hlast = 0.f;

    int tt0 = dir ? 246 : 0;
    float xv[4];
    #pragma unroll
    for (int bi = 0; bi < 4; bi++)
        xv[bi] = g_xproj[((size_t)(b0+bi)*T_ + tt0)*512 + dir*256 + tid];
    __syncthreads();

    for (int s = 0; s < T_; s++){
        u64 acc0 = pack2(xv[0], xv[1]);
        u64 acc1 = pack2(xv[2], xv[3]);

        float xn[4];
        if (s < T_-1){
            int tt2 = dir ? (245 - s) : (s + 1);
            #pragma unroll
            for (int bi = 0; bi < 4; bi++)
                xn[bi] = g_xproj[((size_t)(b0+bi)*T_ + tt2)*512 + dir*256 + tid];
        }

        #pragma unroll
        for (int j4 = 0; j4 < 16; j4++){
            const ulonglong2* hq = (const ulonglong2*)&hs[j4*4][0];
            ulonglong2 h0 = hq[0];
            ulonglong2 h1 = hq[1];
            ulonglong2 h2 = hq[2];
            ulonglong2 h3 = hq[3];
            acc0 = ffma2(wpk[j4*4+0], h0.x, acc0); acc1 = ffma2(wpk[j4*4+0], h0.y, acc1);
            acc0 = ffma2(wpk[j4*4+1], h1.x, acc0); acc1 = ffma2(wpk[j4*4+1], h1.y, acc1);
            acc0 = ffma2(wpk[j4*4+2], h2.x, acc0); acc1 = ffma2(wpk[j4*4+2], h2.y, acc1);
            acc0 = ffma2(wpk[j4*4+3], h3.x, acc0); acc1 = ffma2(wpk[j4*4+3], h3.y, acc1);
        }
        float2 f0 = unpack2(acc0), f1 = unpack2(acc1);
        g_sm[0][tid] = f0.x; g_sm[1][tid] = f0.y;
        g_sm[2][tid] = f1.x; g_sm[3][tid] = f1.y;
        __syncthreads();

        int tv = dir ? (246 - s) : s;
        {
            int bi = tid >> 6, j = tid & 63;
            float gi = sigf(g_sm[bi][j]);
            float gf = sigf(g_sm[bi][64+j]);
            float gc = tanhf(g_sm[bi][128+j]);
            float go = sigf(g_sm[bi][192+j]);
            c = gf*c + gi*gc;
            float h = go * tanhf(c);
            hlast = h;
            hs[j][bi] = h;
            g_values[((size_t)(b0+bi)*T_ + tv)*128 + dir*64 + j] = h;
        }
        __syncthreads();
        #pragma unroll
        for (int bi = 0; bi < 4; bi++) xv[bi] = xn[bi];
    }
    {
        int bi = tid >> 6, j = tid & 63;
        g_hT[dir*B_*64 + (b0+bi)*64 + j] = hlast;
    }
}

// ---------------- h_n build + query ----------------
__global__ void k_hnquery(const float* __restrict__ W2b)
{
    __shared__ float hn[128];
    int b = blockIdx.x, j = threadIdx.x;
    int half = j >> 6, jj = j & 63;
    float v;
    if (b < 256) v = g_hT[(2*b + half)*64 + jj];
    else         v = g_hT[B_*64 + (2*(b-256) + half)*64 + jj];
    hn[j] = v;
    __syncthreads();
    float acc = W2b[j];
    #pragma unroll 4
    for (int k = 0; k < 128; k++) acc += hn[k] * g_W2T[k*128 + j];
    g_query[b*128 + j] = acc;
}

// ---------------- keys GEMM + tanh: M=126464, N=128, K=128 (pipelined) ----------------
__global__ void __launch_bounds__(256,2) k_keys(const float* __restrict__ W1b)
{
    __shared__ u64 As[2][16][130];
    __shared__ u64 Bs[2][16][4][20];
    int tid = threadIdx.x;
    int m0 = blockIdx.x*128;
    int ty = tid/16, tx = tid%16;
    u64 acc[8][4];
    #pragma unroll
    for (int i=0;i<8;i++) for (int j=0;j<4;j++) acc[i][j]=0ull;

    float ra[8], rb[8];
    #pragma unroll
    for (int r = 0; r < 8; r++){
        int i = tid + 256*r;
        ra[r] = g_values[(size_t)(m0+(i>>4))*128 + (i&15)];
        rb[r] = g_W1T[(i>>7)*128 + (i&127)];
    }
    #pragma unroll
    for (int r = 0; r < 8; r++){
        int i = tid + 256*r;
        As[0][i&15][i>>4] = pack2(ra[r], ra[r]);
        bstore(Bs[0], i>>7, i&127, rb[r]);
    }
    __syncthreads();

    #pragma unroll
    for (int c = 0; c < 8; c++){
        if (c < 7){
            int k0 = (c+1)*16;
            #pragma unroll
            for (int r = 0; r < 8; r++){
                int i = tid + 256*r;
                ra[r] = g_values[(size_t)(m0+(i>>4))*128 + k0 + (i&15)];
                rb[r] = g_W1T[(k0+(i>>7))*128 + (i&127)];
            }
        }
        gcomp(As[c&1], Bs[c&1], acc, ty, tx);
        if (c < 7){
            int nb = (c+1)&1;
            #pragma unroll
            for (int r = 0; r < 8; r++){
                int i = tid + 256*r;
                As[nb][i&15][i>>4] = pack2(ra[r], ra[r]);
                bstore(Bs[nb], i>>7, i&127, rb[r]);
            }
        }
        __syncthreads();
    }
    #pragma unroll
    for (int i = 0; i < 8; i++){
        int m = m0 + ty*8 + i;
        int b = m / T_;
        #pragma unroll
        for (int j2 = 0; j2 < 4; j2++){
            float2 f = unpack2(acc[i][j2]);
            int n = tx*8 + j2*2;
            g_E[(size_t)m*128 + n]   = tanhf(f.x + W1b[n]   + g_query[b*128 + n]);
            g_E[(size_t)m*128 + n+1] = tanhf(f.y + W1b[n+1] + g_query[b*128 + n+1]);
        }
    }
}

// ---------------- score GEMM (batched): per b, M=247, N=200, K=128 (pipelined) ----------------
__global__ void __launch_bounds__(256,2) k_scoreK(const float* __restrict__ Vb)
{
    __shared__ u64 As[2][16][130];
    __shared__ u64 Bs[2][16][4][20];
    int tid = threadIdx.x;
    int n0 = blockIdx.x*128, m0 = blockIdx.y*128, b = blockIdx.z;
    int ty = tid/16, tx = tid%16;
    u64 acc[8][4];
    #pragma unroll
    for (int i=0;i<8;i++) for (int j=0;j<4;j++) acc[i][j]=0ull;

    float ra[8], rb[8];
    #pragma unroll
    for (int r = 0; r < 8; r++){
        int i = tid + 256*r;
        ra[r] = (m0+(i>>4) < T_) ? g_E[((size_t)b*T_ + m0+(i>>4))*128 + (i&15)] : 0.f;
        rb[r] = (n0+(i&127) < NTF_) ? g_VT[(i>>7)*NTF_ + n0 + (i&127)] : 0.f;
    }
    #pragma unroll
    for (int r = 0; r < 8; r++){
        int i = tid + 256*r;
        As[0][i&15][i>>4] = pack2(ra[r], ra[r]);
        bstore(Bs[0], i>>7, i&127, rb[r]);
    }
    __syncthreads();

    #pragma unroll
    for (int c = 0; c < 8; c++){
        if (c < 7){
            int k0 = (c+1)*16;
            #pragma unroll
            for (int r = 0; r < 8; r++){
                int i = tid + 256*r;
                ra[r] = (m0+(i>>4) < T_) ? g_E[((size_t)b*T_ + m0+(i>>4))*128 + k0 + (i&15)] : 0.f;
                rb[r] = (n0+(i&127) < NTF_) ? g_VT[(k0+(i>>7))*NTF_ + n0 + (i&127)] : 0.f;
            }
        }
        gcomp(As[c&1], Bs[c&1], acc, ty, tx);
        if (c < 7){
            int nb = (c+1)&1;
            #pragma unroll
            for (int r = 0; r < 8; r++){
                int i = tid + 256*r;
                As[nb][i&15][i>>4] = pack2(ra[r], ra[r]);
                bstore(Bs[nb], i>>7, i&127, rb[r]);
            }
        }
        __syncthreads();
    }
    #pragma unroll
    for (int i = 0; i < 8; i++){
        int m = m0 + ty*8 + i;
        if (m >= T_) continue;
        #pragma unroll
        for (int j2 = 0; j2 < 4; j2++){
            float2 f = unpack2(acc[i][j2]);
            int n = n0 + tx*8 + j2*2;
            if (n < NTF_)
                g_score[((size_t)b*T_ + m)*NTF_ + n] = f.x + Vb[n];
            if (n+1 < NTF_)
                g_score[((size_t)b*T_ + m)*NTF_ + n+1] = f.y + Vb[n+1];
        }
    }
}

// ---------------- softmax over time ----------------
__global__ void k_softmax()
{
    int b = blockIdx.x, k = threadIdx.x;
    if (k >= NTF_) return;
    float* base = g_score + (size_t)b*T_*NTF_ + k;
    float m = -FLT_MAX, s = 0.f;
    for (int t = 0; t < T_; t++){
        float x = base[t*NTF_];
        if (x > m){ s = s*__expf(m - x) + 1.f; m = x; }
        else s += __expf(x - m);
    }
    float inv = 1.f / s;
    for (int t = 0; t < T_; t++){
        float x = base[t*NTF_];
        base[t*NTF_] = __expf(x - m) * inv;
    }
}

// ---------------- context GEMM (batched): per b, M=200, N=128, K=247 (pipelined) ----------------
__global__ void __launch_bounds__(256,2) k_context()
{
    __shared__ u64 As[2][16][130];
    __shared__ u64 Bs[2][16][4][20];
    int tid = threadIdx.x;
    int m0 = blockIdx.x*128, b = blockIdx.y;
    int ty = tid/16, tx = tid%16;
    u64 acc[8][4];
    #pragma unroll
    for (int i=0;i<8;i++) for (int j=0;j<4;j++) acc[i][j]=0ull;

    float ra[8], rb[8];
    #pragma unroll
    for (int r = 0; r < 8; r++){
        int i = tid + 256*r;
        int kA = i >> 7, mA = i & 127;
        ra[r] = (mA + m0 < NTF_) ? g_score[((size_t)b*T_ + kA)*NTF_ + m0 + mA] : 0.f;
        rb[r] = g_values[((size_t)b*T_ + kA)*128 + mA];
    }
    #pragma unroll
    for (int r = 0; r < 8; r++){
        int i = tid + 256*r;
        As[0][i>>7][i&127] = pack2(ra[r], ra[r]);
        bstore(Bs[0], i>>7, i&127, rb[r]);
    }
    __syncthreads();

    for (int c = 0; c < 16; c++){
        if (c < 15){
            int kt0 = (c+1)*16;
            #pragma unroll
            for (int r = 0; r < 8; r++){
                int i = tid + 256*r;
                int kA = kt0 + (i >> 7), mA = i & 127;
                ra[r] = (kA < T_ && mA + m0 < NTF_)
                      ? g_score[((size_t)b*T_ + kA)*NTF_ + m0 + mA] : 0.f;
                rb[r] = (kA < T_)
                      ? g_values[((size_t)b*T_ + kA)*128 + mA] : 0.f;
            }
        }
        gcomp(As[c&1], Bs[c&1], acc, ty, tx);
        if (c < 15){
            int nb = (c+1)&1;
            #pragma unroll
            for (int r = 0; r < 8; r++){
                int i = tid + 256*r;
                As[nb][i>>7][i&127] = pack2(ra[r], ra[r]);
                bstore(Bs[nb], i>>7, i&127, rb[r]);
            }
        }
        __syncthreads();
    }
    #pragma unroll
    for (int i = 0; i < 8; i++){
        int m = m0 + ty*8 + i;
        if (m >= NTF_) continue;
        #pragma unroll
        for (int j2 = 0; j2 < 4; j2++){
            float2 f = unpack2(acc[i][j2]);
            int n = tx*8 + j2*2;
            g_ctx[((size_t)b*NTF_ + m)*128 + n]   = f.x;
            g_ctx[((size_t)b*NTF_ + m)*128 + n+1] = f.y;
        }
    }
}

// ---------------- per-TF heads ----------------
__global__ void __launch_bounds__(256) k_heads(
    const float* __restrict__ fc1w, const float* __restrict__ fc1b,
    const float* __restrict__ fc2w, const float* __restrict__ fc2b,
    float* __restrict__ out)
{
    __shared__ float fw[128][65];
    __shared__ float cs[16][128];
    __shared__ float red[16][65];
    int tid = threadIdx.x;
    int b0 = blockIdx.x*16, k = blockIdx.y;

    for (int i = tid; i < 8192; i += 256){
        int o = i >> 7, d = i & 127;
        fw[d][o] = fc1w[(size_t)k*8192 + i];
    }
    for (int i = tid; i < 2048; i += 256){
        int bi = i >> 7, d = i & 127;
        cs[bi][d] = g_ctx[((size_t)(b0+bi)*NTF_ + k)*128 + d];
    }
    __syncthreads();

    int o = tid & 63;
    float f1b = fc1b[k*64 + o];
    float f2w = fc2w[k*64 + o];
    #pragma unroll
    for (int p = 0; p < 4; p++){
        int bi = (tid >> 6) + p*4;
        float acc = 0.f;
        #pragma unroll
        for (int d4 = 0; d4 < 32; d4++){
            float4 cv = *(const float4*)&cs[bi][d4*4];
            acc += fw[d4*4+0][o]*cv.x + fw[d4*4+1][o]*cv.y
                 + fw[d4*4+2][o]*cv.z + fw[d4*4+3][o]*cv.w;
        }
        float h1 = fmaxf(acc + f1b, 0.f);
        red[bi][o] = h1 * f2w;
    }
    __syncthreads();
    if (tid < 16){
        float s = fc2b[k];
        #pragma unroll 8
        for (int oo = 0; oo < 64; oo++) s += red[tid][oo];
        out[(size_t)(b0 + tid)*NTF_ + k] = s;
    }
}

// ---------------- launch ----------------
extern "C" void kernel_launch(void* const* d_in, const int* in_sizes, int n_in,
                              void* d_out, int out_size)
{
    const float* DNA    = (const float*)d_in[0];
    const float* c0w    = (const float*)d_in[1];
    const float* c0b    = (const float*)d_in[2];
    const float* bn0g   = (const float*)d_in[3];
    const float* bn0b   = (const float*)d_in[4];
    const float* bn0m   = (const float*)d_in[5];
    const float* bn0v   = (const float*)d_in[6];
    const float* c1w    = (const float*)d_in[7];
    const float* c1b    = (const float*)d_in[8];
    const float* bn1g   = (const float*)d_in[9];
    const float* bn1b   = (const float*)d_in[10];
    const float* bn1m   = (const float*)d_in[11];
    const float* bn1v   = (const float*)d_in[12];
    const float* wih_f  = (const float*)d_in[13];
    const float* whh_f  = (const float*)d_in[14];
    const float* bih_f  = (const float*)d_in[15];
    const float* bhh_f  = (const float*)d_in[16];
    const float* wih_b  = (const float*)d_in[17];
    const float* whh_b  = (const float*)d_in[18];
    const float* bih_b  = (const float*)d_in[19];
    const float* bhh_b  = (const float*)d_in[20];
    const float* W1w    = (const float*)d_in[21];
    const float* W1b    = (const float*)d_in[22];
    const float* W2w    = (const float*)d_in[23];
    const float* W2b    = (const float*)d_in[24];
    const float* Vw     = (const float*)d_in[25];
    const float* Vb     = (const float*)d_in[26];
    const float* fc1w   = (const float*)d_in[27];
    const float* fc1b   = (const float*)d_in[28];
    const float* fc2w   = (const float*)d_in[29];
    const float* fc2b   = (const float*)d_in[30];
    float* out = (float*)d_out;

    k_prep<<<512, 256>>>(W1w, W2w, Vw, wih_f, wih_b, bih_f, bhh_f, bih_b, bhh_b, c1w);
    k_conv0<<<512, 256>>>(DNA, c0w, c0b, bn0g, bn0b, bn0m, bn0v);
    k_conv1<<<988, 256>>>(c1b, bn1g, bn1b, bn1m, bn1v);
    k_xproj<<<dim3(4, 988), 256>>>();
    k_lstm<<<256, 256>>>(whh_f, whh_b);
    k_hnquery<<<512, 128>>>(W2b);
    k_keys<<<988, 256>>>(W1b);
    k_scoreK<<<dim3(2, 2, 512), 256>>>(Vb);
    k_softmax<<<512, 256>>>();
    k_context<<<dim3(2, 512), 256>>>();
    k_heads<<<dim3(32, 200), 256>>>(fc1w, fc1b, fc2w, fc2b, out);
}

// round 8
// speedup vs baseline: 1.1539x; 1.1539x over previous
#include <cuda_runtime.h>
#include <math.h>
#include <float.h>

#define B_    512
#define T_    247
#define C_    64
#define NTF_  200
#define LPOOL 254
#define MROWS (B_*T_)      // 126464

typedef unsigned long long u64;

// ---------------- scratch ----------------
__device__ float g_pooled[B_*C_*LPOOL];
__device__ float g_xlstm [MROWS*C_];
__device__ float g_xproj [(size_t)MROWS*512];
__device__ float g_values[MROWS*128];
__device__ float g_hT    [2*B_*64];
__device__ float g_query [B_*128];
__device__ float g_E     [MROWS*128];
__device__ float g_score [MROWS*NTF_];
__device__ float g_ctx   [B_*NTF_*128];
__device__ float g_W1T [128*128];
__device__ float g_W2T [128*128];
__device__ float g_VT  [128*NTF_];
__device__ float g_WIHT[64*512];
__device__ float g_biasIH[512];
__device__ float g_c1wT[512*64];

__device__ __forceinline__ float sigf(float x){ return 1.f/(1.f+__expf(-x)); }

// ---- packed fp32x2 helpers (FFMA2) — used by conv1 + lstm ----
__device__ __forceinline__ u64 ffma2(u64 a, u64 b, u64 c){
    u64 d;
    asm("fma.rn.f32x2 %0, %1, %2, %3;" : "=l"(d) : "l"(a), "l"(b), "l"(c));
    return d;
}
__device__ __forceinline__ u64 pack2(float x, float y){
    u64 d;
    asm("mov.b64 %0, {%1, %2};" : "=l"(d) : "f"(x), "f"(y));
    return d;
}
__device__ __forceinline__ float2 unpack2(u64 d){
    float2 f;
    asm("mov.b64 {%0, %1}, %2;" : "=f"(f.x), "=f"(f.y) : "l"(d));
    return f;
}

// ---- tf32 split-precision MMA helpers ----
__device__ __forceinline__ void tf32split(float x, unsigned &h, unsigned &l){
    asm("cvt.rna.tf32.f32 %0, %1;" : "=r"(h) : "f"(x));
    float lf = x - __uint_as_float(h);
    asm("cvt.rna.tf32.f32 %0, %1;" : "=r"(l) : "f"(lf));
}
__device__ __forceinline__ void mma8(float *d, const uint4 &a, const uint2 &b){
    asm volatile("mma.sync.aligned.m16n8k8.row.col.f32.tf32.tf32.f32 "
        "{%0,%1,%2,%3}, {%4,%5,%6,%7}, {%8,%9}, {%0,%1,%2,%3};"
        : "+f"(d[0]), "+f"(d[1]), "+f"(d[2]), "+f"(d[3])
        : "r"(a.x), "r"(a.y), "r"(a.z), "r"(a.w), "r"(b.x), "r"(b.y));
}

// fragment-permuted smem tiles: 128x16 per operand, hi+lo
struct TSmem {
    unsigned Ah[2][8][32][4], Al[2][8][32][4];   // [kb][mtile][lane][reg]
    unsigned Bh[2][16][33][2], Bl[2][16][33][2]; // [kb][ntile][lane(+pad)][reg]
};

__device__ __forceinline__ void astoreT(TSmem &S, int m, int k, float x){
    unsigned h, l; tf32split(x, h, l);
    int kb = k>>3, c = k&7, mt = m>>4, r8 = m&15;
    int t = (r8&7)*4 + (c&3), v = ((c>>2)<<1) | (r8>>3);
    S.Ah[kb][mt][t][v] = h; S.Al[kb][mt][t][v] = l;
}
__device__ __forceinline__ void bstoreT(TSmem &S, int k, int n, float x){
    unsigned h, l; tf32split(x, h, l);
    int kb = k>>3, nt = n>>3, t = (n&7)*4 + (k&3), v = (k>>2)&1;
    S.Bh[kb][nt][t][v] = h; S.Bl[kb][nt][t][v] = l;
}

__device__ __forceinline__ void tcomp(const TSmem &S, float (&acc)[4][4][4],
                                      int lane, int wm, int wn)
{
    #pragma unroll
    for (int kb = 0; kb < 2; kb++){
        uint2 bh[4], bl[4];
        #pragma unroll
        for (int j = 0; j < 4; j++){
            int nt = wn*4 + j;
            bh[j] = *(const uint2*)&S.Bh[kb][nt][lane][0];
            bl[j] = *(const uint2*)&S.Bl[kb][nt][lane][0];
        }
        #pragma unroll
        for (int i = 0; i < 4; i++){
            int mt = wm*4 + i;
            uint4 ah = *(const uint4*)&S.Ah[kb][mt][lane][0];
            uint4 al = *(const uint4*)&S.Al[kb][mt][lane][0];
            #pragma unroll
            for (int j = 0; j < 4; j++){
                mma8(acc[i][j], ah, bh[j]);
                mma8(acc[i][j], ah, bl[j]);
                mma8(acc[i][j], al, bh[j]);
            }
        }
    }
}

// ---------------- prep ----------------
__global__ void k_prep(const float* __restrict__ W1, const float* __restrict__ W2,
                       const float* __restrict__ V,
                       const float* __restrict__ wih_f, const float* __restrict__ wih_b,
                       const float* __restrict__ bih_f, const float* __restrict__ bhh_f,
                       const float* __restrict__ bih_b, const float* __restrict__ bhh_b,
                       const float* __restrict__ c1w)
{
    int idx = blockIdx.x*blockDim.x + threadIdx.x;
    if (idx < 16384){ int n = idx/128, k = idx%128; g_W1T[k*128+n] = W1[idx]; }
    if (idx < 16384){ int n = idx/128, k = idx%128; g_W2T[k*128+n] = W2[idx]; }
    if (idx < 128*NTF_){ int n = idx/128, k = idx%128; g_VT[k*NTF_+n] = V[idx]; }
    if (idx < 16384){ int g = idx/64, k = idx%64;
        g_WIHT[k*512 + g]       = wih_f[idx];
        g_WIHT[k*512 + 256 + g] = wih_b[idx]; }
    if (idx < 512){ g_biasIH[idx] = (idx < 256) ? (bih_f[idx] + bhh_f[idx])
                                                : (bih_b[idx-256] + bhh_b[idx-256]); }
    if (idx < 32768){ int c = idx/512, k = idx%512; g_c1wT[k*64+c] = c1w[idx]; }
}

// ---------------- conv0 + bn + relu + maxpool4 ----------------
__global__ void __launch_bounds__(256) k_conv0(
    const float* __restrict__ x, const float* __restrict__ w, const float* __restrict__ cb,
    const float* __restrict__ g, const float* __restrict__ bb,
    const float* __restrict__ mm, const float* __restrict__ vv)
{
    __shared__ float4 xs4[1024];
    int b = blockIdx.x, tid = threadIdx.x;
    const float4* in4 = (const float4*)(x + (size_t)b*4096);
    for (int i = tid; i < 1024; i += 256) xs4[i] = in4[i];

    int c = tid & 63;
    float4 wr[8];
    #pragma unroll
    for (int kk = 0; kk < 8; kk++)
        wr[kk] = make_float4(w[c*32 + 0*8 + kk], w[c*32 + 1*8 + kk],
                             w[c*32 + 2*8 + kk], w[c*32 + 3*8 + kk]);
    float scale = g[c] * rsqrtf(vv[c] + 1e-5f);
    float shift = bb[c] - mm[c]*scale;
    float cbc   = cb[c];
    __syncthreads();

    for (int idx = tid; idx < 64*LPOOL; idx += 256){
        int q = idx >> 6;
        float best = -FLT_MAX;
        #pragma unroll
        for (int dp = 0; dp < 4; dp++){
            int p = 4*q + dp;
            float acc = cbc;
            #pragma unroll
            for (int kk = 0; kk < 8; kk++){
                float4 xv = xs4[p+kk];
                acc += wr[kk].x*xv.x + wr[kk].y*xv.y + wr[kk].z*xv.z + wr[kk].w*xv.w;
            }
            best = fmaxf(best, acc*scale + shift);
        }
        g_pooled[(b*64 + c)*LPOOL + q] = fmaxf(best, 0.f);
    }
}

// ---------------- conv1 GEMM (FFMA2, R6 version): M=126464, N=64, K=512 ----------------
__global__ void __launch_bounds__(256,2) k_conv1(
    const float* __restrict__ cb,
    const float* __restrict__ gg, const float* __restrict__ bb,
    const float* __restrict__ mm, const float* __restrict__ vv)
{
    __shared__ float As[2][16][132];
    __shared__ u64  Bs[2][16][2][20];
    int tid = threadIdx.x;
    int m0  = blockIdx.x*128;
    int ty = tid/16, tx = tid%16;
    u64 acc[8][2];
    #pragma unroll
    for (int i=0;i<8;i++){ acc[i][0]=0ull; acc[i][1]=0ull; }

    int bzl[8], tl[8];
    #pragma unroll
    for (int r = 0; r < 8; r++){
        int i = tid + 256*r;
        int gm = m0 + (i >> 4);
        bzl[r] = gm / T_;
        tl[r]  = gm - bzl[r]*T_;
    }

    float ra[8], rb[4];
    #pragma unroll
    for (int r = 0; r < 8; r++){
        int i = tid + 256*r; int kg = i & 15;
        ra[r] = g_pooled[(bzl[r]*64 + (kg>>3))*LPOOL + tl[r] + (kg&7)];
    }
    #pragma unroll
    for (int r = 0; r < 4; r++){
        int i = tid + 256*r;
        rb[r] = g_c1wT[(i>>6)*64 + (i&63)];
    }
    #pragma unroll
    for (int r = 0; r < 8; r++){ int i = tid + 256*r; As[0][i&15][i>>4] = ra[r]; }
    #pragma unroll
    for (int r = 0; r < 4; r++){
        int i = tid + 256*r; int n = i & 63, k = i >> 6;
        ((float*)&Bs[0][k][(n>>1)&1][n>>2])[n&1] = rb[r];
    }
    __syncthreads();

    for (int c = 0; c < 32; c++){
        if (c < 31){
            int k0 = (c+1)*16;
            #pragma unroll
            for (int r = 0; r < 8; r++){
                int i = tid + 256*r; int kg = k0 + (i & 15);
                ra[r] = g_pooled[(bzl[r]*64 + (kg>>3))*LPOOL + tl[r] + (kg&7)];
            }
            #pragma unroll
            for (int r = 0; r < 4; r++){
                int i = tid + 256*r;
                rb[r] = g_c1wT[(k0 + (i>>6))*64 + (i&63)];
            }
        }
        {
            const float (&A)[16][132] = As[c&1];
            const u64 (&Bv)[16][2][20] = Bs[c&1];
            #pragma unroll
            for (int k = 0; k < 16; k++){
                float4 a0 = *(const float4*)&A[k][ty*8];
                float4 a1 = *(const float4*)&A[k][ty*8+4];
                u64 b0 = Bv[k][0][tx];
                u64 b1 = Bv[k][1][tx];
                float av[8] = {a0.x,a0.y,a0.z,a0.w,a1.x,a1.y,a1.z,a1.w};
                #pragma unroll
                for (int i = 0; i < 8; i++){
                    u64 ai = pack2(av[i], av[i]);
                    acc[i][0] = ffma2(ai, b0, acc[i][0]);
                    acc[i][1] = ffma2(ai, b1, acc[i][1]);
                }
            }
        }
        if (c < 31){
            int nb = (c+1)&1;
            #pragma unroll
            for (int r = 0; r < 8; r++){ int i = tid + 256*r; As[nb][i&15][i>>4] = ra[r]; }
            #pragma unroll
            for (int r = 0; r < 4; r++){
                int i = tid + 256*r; int n = i & 63, k = i >> 6;
                ((float*)&Bs[nb][k][(n>>1)&1][n>>2])[n&1] = rb[r];
            }
        }
        __syncthreads();
    }
    #pragma unroll
    for (int j2 = 0; j2 < 2; j2++){
        #pragma unroll
        for (int h = 0; h < 2; h++){
            int c = tx*4 + j2*2 + h;
            float scale = gg[c] * rsqrtf(vv[c] + 1e-5f);
            float shift = bb[c] + (cb[c] - mm[c])*scale;
            #pragma unroll
            for (int i = 0; i < 8; i++){
                int m = m0 + ty*8 + i;
                float2 f = unpack2(acc[i][j2]);
                float v = h ? f.y : f.x;
                g_xlstm[(size_t)m*64 + c] = fmaxf(v*scale + shift, 0.f);
            }
        }
    }
}

// ---------------- xproj GEMM (tf32 MMA): M=126464, N=512, K=64 ----------------
__global__ void __launch_bounds__(256) k_xproj()
{
    __shared__ TSmem S;
    int tid = threadIdx.x, lane = tid&31, w = tid>>5, wm = w>>2, wn = w&3;
    int n0 = blockIdx.x*128, m0 = blockIdx.y*128;
    float acc[4][4][4];
    #pragma unroll
    for (int i=0;i<4;i++) for (int j=0;j<4;j++) for (int v=0;v<4;v++) acc[i][j][v]=0.f;

    #pragma unroll
    for (int k0 = 0; k0 < 64; k0 += 16){
        #pragma unroll
        for (int r = 0; r < 8; r++){
            int i = tid + 256*r; int m = i>>4, k = i&15;
            astoreT(S, m, k, g_xlstm[(size_t)(m0+m)*64 + k0+k]);
        }
        #pragma unroll
        for (int r = 0; r < 8; r++){
            int i = tid + 256*r; int k = i>>7, n = i&127;
            bstoreT(S, k, n, g_WIHT[(k0+k)*512 + n0+n]);
        }
        __syncthreads();
        tcomp(S, acc, lane, wm, wn);
        __syncthreads();
    }
    int g = lane>>2, tc = lane&3;
    #pragma unroll
    for (int i=0;i<4;i++)
      #pragma unroll
      for (int j=0;j<4;j++)
        #pragma unroll
        for (int r2=0;r2<2;r2++){
            int row = m0 + wm*64 + i*16 + g + 8*r2;
            int col = n0 + wn*32 + j*8 + tc*2;
            float2 o = make_float2(acc[i][j][r2*2+0] + g_biasIH[col],
                                   acc[i][j][r2*2+1] + g_biasIH[col+1]);
            *(float2*)&g_xproj[(size_t)row*512 + col] = o;
        }
}

// ---------------- LSTM recurrence (persistent, f32x2, R6 version) ----------------
__global__ void __launch_bounds__(256) k_lstm(const float* __restrict__ whh_f,
                                              const float* __restrict__ whh_b)
{
    __shared__ float hs[64][4];
    __shared__ float g_sm[4][256];
    int dir = blockIdx.x >> 7;
    int b0  = (blockIdx.x & 127) * 4;
    int tid = threadIdx.x;
    const float* whh = dir ? whh_b : whh_f;

    float4 w4[16];
    #pragma unroll
    for (int j4 = 0; j4 < 16; j4++) w4[j4] = *(const float4*)&whh[tid*64 + j4*4];

    hs[tid>>2][tid&3] = 0.f;
    float c = 0.f, hlast = 0.f;

    int tt0 = dir ? 246 : 0;
    float xv[4];
    #pragma unroll
    for (int bi = 0; bi < 4; bi++)
        xv[bi] = g_xproj[((size_t)(b0+bi)*T_ + tt0)*512 + dir*256 + tid];
    __syncthreads();

    for (int s = 0; s < T_; s++){
        u64 acc0 = pack2(xv[0], xv[1]);
        u64 acc1 = pack2(xv[2], xv[3]);

        float xn[4];
        if (s < T_-1){
            int tt2 = dir ? (245 - s) : (s + 1);
            #pragma unroll
            for (int bi = 0; bi < 4; bi++)
                xn[bi] = g_xproj[((size_t)(b0+bi)*T_ + tt2)*512 + dir*256 + tid];
        }

        #pragma unroll
        for (int j4 = 0; j4 < 16; j4++){
            float4 w = w4[j4];
            const ulonglong2* hq = (const ulonglong2*)&hs[j4*4][0];
            ulonglong2 h0 = hq[0];
            ulonglong2 h1 = hq[1];
            ulonglong2 h2 = hq[2];
            ulonglong2 h3 = hq[3];
            u64 wx = pack2(w.x, w.x);
            u64 wy = pack2(w.y, w.y);
            u64 wz = pack2(w.z, w.z);
            u64 ww = pack2(w.w, w.w);
            acc0 = ffma2(wx, h0.x, acc0); acc1 = ffma2(wx, h0.y, acc1);
            acc0 = ffma2(wy, h1.x, acc0); acc1 = ffma2(wy, h1.y, acc1);
            acc0 = ffma2(wz, h2.x, acc0); acc1 = ffma2(wz, h2.y, acc1);
            acc0 = ffma2(ww, h3.x, acc0); acc1 = ffma2(ww, h3.y, acc1);
        }
        float2 f0 = unpack2(acc0), f1 = unpack2(acc1);
        g_sm[0][tid] = f0.x; g_sm[1][tid] = f0.y;
        g_sm[2][tid] = f1.x; g_sm[3][tid] = f1.y;
        __syncthreads();

        int tv = dir ? (246 - s) : s;
        {
            int bi = tid >> 6, j = tid & 63;
            float gi = sigf(g_sm[bi][j]);
            float gf = sigf(g_sm[bi][64+j]);
            float gc = tanhf(g_sm[bi][128+j]);
            float go = sigf(g_sm[bi][192+j]);
            c = gf*c + gi*gc;
            float h = go * tanhf(c);
            hlast = h;
            hs[j][bi] = h;
            g_values[((size_t)(b0+bi)*T_ + tv)*128 + dir*64 + j] = h;
        }
        __syncthreads();
        #pragma unroll
        for (int bi = 0; bi < 4; bi++) xv[bi] = xn[bi];
    }
    {
        int bi = tid >> 6, j = tid & 63;
        g_hT[dir*B_*64 + (b0+bi)*64 + j] = hlast;
    }
}

// ---------------- h_n build + query ----------------
__global__ void k_hnquery(const float* __restrict__ W2b)
{
    __shared__ float hn[128];
    int b = blockIdx.x, j = threadIdx.x;
    int half = j >> 6, jj = j & 63;
    float v;
    if (b < 256) v = g_hT[(2*b + half)*64 + jj];
    else         v = g_hT[B_*64 + (2*(b-256) + half)*64 + jj];
    hn[j] = v;
    __syncthreads();
    float acc = W2b[j];
    #pragma unroll 4
    for (int k = 0; k < 128; k++) acc += hn[k] * g_W2T[k*128 + j];
    g_query[b*128 + j] = acc;
}

// ---------------- keys GEMM + tanh (tf32 MMA): M=126464, N=128, K=128 ----------------
__global__ void __launch_bounds__(256) k_keys(const float* __restrict__ W1b)
{
    __shared__ TSmem S;
    int tid = threadIdx.x, lane = tid&31, w = tid>>5, wm = w>>2, wn = w&3;
    int m0 = blockIdx.x*128;
    float acc[4][4][4];
    #pragma unroll
    for (int i=0;i<4;i++) for (int j=0;j<4;j++) for (int v=0;v<4;v++) acc[i][j][v]=0.f;

    #pragma unroll
    for (int k0 = 0; k0 < 128; k0 += 16){
        #pragma unroll
        for (int r = 0; r < 8; r++){
            int i = tid + 256*r; int m = i>>4, k = i&15;
            astoreT(S, m, k, g_values[(size_t)(m0+m)*128 + k0+k]);
        }
        #pragma unroll
        for (int r = 0; r < 8; r++){
            int i = tid + 256*r; int k = i>>7, n = i&127;
            bstoreT(S, k, n, g_W1T[(k0+k)*128 + n]);
        }
        __syncthreads();
        tcomp(S, acc, lane, wm, wn);
        __syncthreads();
    }
    int g = lane>>2, tc = lane&3;
    #pragma unroll
    for (int i=0;i<4;i++)
      #pragma unroll
      for (int j=0;j<4;j++)
        #pragma unroll
        for (int r2=0;r2<2;r2++){
            int row = m0 + wm*64 + i*16 + g + 8*r2;
            int b = row / T_;
            int col = wn*32 + j*8 + tc*2;
            float e0 = tanhf(acc[i][j][r2*2+0] + W1b[col]   + g_query[b*128 + col]);
            float e1 = tanhf(acc[i][j][r2*2+1] + W1b[col+1] + g_query[b*128 + col+1]);
            *(float2*)&g_E[(size_t)row*128 + col] = make_float2(e0, e1);
        }
}

// ---------------- score GEMM (tf32 MMA, batched): per b, M=247, N=200, K=128 ----------------
__global__ void __launch_bounds__(256) k_scoreK(const float* __restrict__ Vb)
{
    __shared__ TSmem S;
    int tid = threadIdx.x, lane = tid&31, w = tid>>5, wm = w>>2, wn = w&3;
    int n0 = blockIdx.x*128, m0 = blockIdx.y*128, b = blockIdx.z;
    float acc[4][4][4];
    #pragma unroll
    for (int i=0;i<4;i++) for (int j=0;j<4;j++) for (int v=0;v<4;v++) acc[i][j][v]=0.f;

    #pragma unroll
    for (int k0 = 0; k0 < 128; k0 += 16){
        #pragma unroll
        for (int r = 0; r < 8; r++){
            int i = tid + 256*r; int m = i>>4, k = i&15;
            float x = (m0+m < T_) ? g_E[((size_t)b*T_ + m0+m)*128 + k0+k] : 0.f;
            astoreT(S, m, k, x);
        }
        #pragma unroll
        for (int r = 0; r < 8; r++){
            int i = tid + 256*r; int k = i>>7, n = i&127;
            float x = (n0+n < NTF_) ? g_VT[(k0+k)*NTF_ + n0+n] : 0.f;
            bstoreT(S, k, n, x);
        }
        __syncthreads();
        tcomp(S, acc, lane, wm, wn);
        __syncthreads();
    }
    int g = lane>>2, tc = lane&3;
    #pragma unroll
    for (int i=0;i<4;i++)
      #pragma unroll
      for (int j=0;j<4;j++)
        #pragma unroll
        for (int r2=0;r2<2;r2++){
            int row = m0 + wm*64 + i*16 + g + 8*r2;
            int col = n0 + wn*32 + j*8 + tc*2;
            if (row < T_ && col < NTF_){
                float2 o = make_float2(acc[i][j][r2*2+0] + Vb[col],
                                       acc[i][j][r2*2+1] + Vb[col+1]);
                *(float2*)&g_score[((size_t)b*T_ + row)*NTF_ + col] = o;
            }
        }
}

// ---------------- softmax over time ----------------
__global__ void k_softmax()
{
    int b = blockIdx.x, k = threadIdx.x;
    if (k >= NTF_) return;
    float* base = g_score + (size_t)b*T_*NTF_ + k;
    float m = -FLT_MAX, s = 0.f;
    for (int t = 0; t < T_; t++){
        float x = base[t*NTF_];
        if (x > m){ s = s*__expf(m - x) + 1.f; m = x; }
        else s += __expf(x - m);
    }
    float inv = 1.f / s;
    for (int t = 0; t < T_; t++){
        float x = base[t*NTF_];
        base[t*NTF_] = __expf(x - m) * inv;
    }
}

// ---------------- context GEMM (tf32 MMA, batched): per b, M=200, N=128, K=247 ----------------
__global__ void __launch_bounds__(256) k_context()
{
    __shared__ TSmem S;
    int tid = threadIdx.x, lane = tid&31, w = tid>>5, wm = w>>2, wn = w&3;
    int m0 = blockIdx.x*128, b = blockIdx.y;
    float acc[4][4][4];
    #pragma unroll
    for (int i=0;i<4;i++) for (int j=0;j<4;j++) for (int v=0;v<4;v++) acc[i][j][v]=0.f;

    for (int k0 = 0; k0 < 256; k0 += 16){
        #pragma unroll
        for (int r = 0; r < 8; r++){
            int i = tid + 256*r; int m = i&127, k = i>>7;
            float x = (k0+k < T_ && m0+m < NTF_)
                    ? g_score[((size_t)b*T_ + k0+k)*NTF_ + m0+m] : 0.f;
            astoreT(S, m, k, x);
        }
        #pragma unroll
        for (int r = 0; r < 8; r++){
            int i = tid + 256*r; int k = i>>7, n = i&127;
            float x = (k0+k < T_) ? g_values[((size_t)b*T_ + k0+k)*128 + n] : 0.f;
            bstoreT(S, k, n, x);
        }
        __syncthreads();
        tcomp(S, acc, lane, wm, wn);
        __syncthreads();
    }
    int g = lane>>2, tc = lane&3;
    #pragma unroll
    for (int i=0;i<4;i++)
      #pragma unroll
      for (int j=0;j<4;j++)
        #pragma unroll
        for (int r2=0;r2<2;r2++){
            int row = m0 + wm*64 + i*16 + g + 8*r2;
            int col = wn*32 + j*8 + tc*2;
            if (row < NTF_){
                float2 o = make_float2(acc[i][j][r2*2+0], acc[i][j][r2*2+1]);
                *(float2*)&g_ctx[((size_t)b*NTF_ + row)*128 + col] = o;
            }
        }
}

// ---------------- per-TF heads ----------------
__global__ void __launch_bounds__(256) k_heads(
    const float* __restrict__ fc1w, const float* __restrict__ fc1b,
    const float* __restrict__ fc2w, const float* __restrict__ fc2b,
    float* __restrict__ out)
{
    __shared__ float fw[128][65];
    __shared__ float cs[16][128];
    __shared__ float red[16][65];
    int tid = threadIdx.x;
    int b0 = blockIdx.x*16, k = blockIdx.y;

    for (int i = tid; i < 8192; i += 256){
        int o = i >> 7, d = i & 127;
        fw[d][o] = fc1w[(size_t)k*8192 + i];
    }
    for (int i = tid; i < 2048; i += 256){
        int bi = i >> 7, d = i & 127;
        cs[bi][d] = g_ctx[((size_t)(b0+bi)*NTF_ + k)*128 + d];
    }
    __syncthreads();

    int o = tid & 63;
    float f1b = fc1b[k*64 + o];
    float f2w = fc2w[k*64 + o];
    #pragma unroll
    for (int p = 0; p < 4; p++){
        int bi = (tid >> 6) + p*4;
        float acc = 0.f;
        #pragma unroll
        for (int d4 = 0; d4 < 32; d4++){
            float4 cv = *(const float4*)&cs[bi][d4*4];
            acc += fw[d4*4+0][o]*cv.x + fw[d4*4+1][o]*cv.y
                 + fw[d4*4+2][o]*cv.z + fw[d4*4+3][o]*cv.w;
        }
        float h1 = fmaxf(acc + f1b, 0.f);
        red[bi][o] = h1 * f2w;
    }
    __syncthreads();
    if (tid < 16){
        float s = fc2b[k];
        #pragma unroll 8
        for (int oo = 0; oo < 64; oo++) s += red[tid][oo];
        out[(size_t)(b0 + tid)*NTF_ + k] = s;
    }
}

// ---------------- launch ----------------
extern "C" void kernel_launch(void* const* d_in, const int* in_sizes, int n_in,
                              void* d_out, int out_size)
{
    const float* DNA    = (const float*)d_in[0];
    const float* c0w    = (const float*)d_in[1];
    const float* c0b    = (const float*)d_in[2];
    const float* bn0g   = (const float*)d_in[3];
    const float* bn0b   = (const float*)d_in[4];
    const float* bn0m   = (const float*)d_in[5];
    const float* bn0v   = (const float*)d_in[6];
    const float* c1w    = (const float*)d_in[7];
    const float* c1b    = (const float*)d_in[8];
    const float* bn1g   = (const float*)d_in[9];
    const float* bn1b   = (const float*)d_in[10];
    const float* bn1m   = (const float*)d_in[11];
    const float* bn1v   = (const float*)d_in[12];
    const float* wih_f  = (const float*)d_in[13];
    const float* whh_f  = (const float*)d_in[14];
    const float* bih_f  = (const float*)d_in[15];
    const float* bhh_f  = (const float*)d_in[16];
    const float* wih_b  = (const float*)d_in[17];
    const float* whh_b  = (const float*)d_in[18];
    const float* bih_b  = (const float*)d_in[19];
    const float* bhh_b  = (const float*)d_in[20];
    const float* W1w    = (const float*)d_in[21];
    const float* W1b    = (const float*)d_in[22];
    const float* W2w    = (const float*)d_in[23];
    const float* W2b    = (const float*)d_in[24];
    const float* Vw     = (const float*)d_in[25];
    const float* Vb     = (const float*)d_in[26];
    const float* fc1w   = (const float*)d_in[27];
    const float* fc1b   = (const float*)d_in[28];
    const float* fc2w   = (const float*)d_in[29];
    const float* fc2b   = (const float*)d_in[30];
    float* out = (float*)d_out;

    k_prep<<<512, 256>>>(W1w, W2w, Vw, wih_f, wih_b, bih_f, bhh_f, bih_b, bhh_b, c1w);
    k_conv0<<<512, 256>>>(DNA, c0w, c0b, bn0g, bn0b, bn0m, bn0v);
    k_conv1<<<988, 256>>>(c1b, bn1g, bn1b, bn1m, bn1v);
    k_xproj<<<dim3(4, 988), 256>>>();
    k_lstm<<<256, 256>>>(whh_f, whh_b);
    k_hnquery<<<512, 128>>>(W2b);
    k_keys<<<988, 256>>>(W1b);
    k_scoreK<<<dim3(2, 2, 512), 256>>>(Vb);
    k_softmax<<<512, 256>>>();
    k_context<<<dim3(2, 512), 256>>>();
    k_heads<<<dim3(32, 200), 256>>>(fc1w, fc1b, fc2w, fc2b, out);
}

// round 9
// speedup vs baseline: 1.2364x; 1.0714x over previous
#include <cuda_runtime.h>
#include <math.h>
#include <float.h>

#define B_    512
#define T_    247
#define C_    64
#define NTF_  200
#define LPOOL 254
#define MROWS (B_*T_)      // 126464

typedef unsigned long long u64;

// ---------------- scratch ----------------
__device__ float g_pooled[B_*C_*LPOOL];
__device__ float g_xlstm [MROWS*C_];
__device__ float g_xproj [(size_t)MROWS*512];
__device__ float g_values[MROWS*128];
__device__ float g_hT    [2*B_*64];
__device__ float g_query [B_*128];
__device__ float g_E     [MROWS*128];
__device__ float g_score [MROWS*NTF_];
__device__ float g_ctx   [B_*NTF_*128];
__device__ float g_W1T [128*128];
__device__ float g_W2T [128*128];
__device__ float g_VT  [128*NTF_];
__device__ float g_WIHT[64*512];
__device__ float g_biasIH[512];
__device__ float g_c1wT[512*64];

__device__ __forceinline__ float sigf(float x){ return 1.f/(1.f+__expf(-x)); }

// ---- packed fp32x2 helpers (FFMA2) — used by lstm ----
__device__ __forceinline__ u64 ffma2(u64 a, u64 b, u64 c){
    u64 d;
    asm("fma.rn.f32x2 %0, %1, %2, %3;" : "=l"(d) : "l"(a), "l"(b), "l"(c));
    return d;
}
__device__ __forceinline__ u64 pack2(float x, float y){
    u64 d;
    asm("mov.b64 %0, {%1, %2};" : "=l"(d) : "f"(x), "f"(y));
    return d;
}
__device__ __forceinline__ float2 unpack2(u64 d){
    float2 f;
    asm("mov.b64 {%0, %1}, %2;" : "=f"(f.x), "=f"(f.y) : "l"(d));
    return f;
}

// ---- tf32 split-precision MMA helpers ----
__device__ __forceinline__ void tf32split(float x, unsigned &h, unsigned &l){
    asm("cvt.rna.tf32.f32 %0, %1;" : "=r"(h) : "f"(x));
    float lf = x - __uint_as_float(h);
    asm("cvt.rna.tf32.f32 %0, %1;" : "=r"(l) : "f"(lf));
}
__device__ __forceinline__ void mma8(float *d, const uint4 &a, const uint2 &b){
    asm volatile("mma.sync.aligned.m16n8k8.row.col.f32.tf32.tf32.f32 "
        "{%0,%1,%2,%3}, {%4,%5,%6,%7}, {%8,%9}, {%0,%1,%2,%3};"
        : "+f"(d[0]), "+f"(d[1]), "+f"(d[2]), "+f"(d[3])
        : "r"(a.x), "r"(a.y), "r"(a.z), "r"(a.w), "r"(b.x), "r"(b.y));
}

// fragment-permuted smem tiles: 128x16 per operand, hi+lo
struct TSmem {
    unsigned Ah[2][8][32][4], Al[2][8][32][4];   // [kb][mtile][lane][reg]
    unsigned Bh[2][16][33][2], Bl[2][16][33][2]; // [kb][ntile][lane(+pad)][reg]
};
// conv1 variant: N=64 -> 8 n-tiles
struct TSmemC {
    unsigned Ah[2][8][32][4], Al[2][8][32][4];
    unsigned Bh[2][8][33][2], Bl[2][8][33][2];
};

__device__ __forceinline__ void astoreT(unsigned (&Ah)[2][8][32][4], unsigned (&Al)[2][8][32][4],
                                        int m, int k, float x){
    unsigned h, l; tf32split(x, h, l);
    int kb = k>>3, c = k&7, mt = m>>4, r8 = m&15;
    int t = (r8&7)*4 + (c&3), v = ((c>>2)<<1) | (r8>>3);
    Ah[kb][mt][t][v] = h; Al[kb][mt][t][v] = l;
}
__device__ __forceinline__ void bstoreT(unsigned (&Bh)[2][16][33][2], unsigned (&Bl)[2][16][33][2],
                                        int k, int n, float x){
    unsigned h, l; tf32split(x, h, l);
    int kb = k>>3, nt = n>>3, t = (n&7)*4 + (k&3), v = (k>>2)&1;
    Bh[kb][nt][t][v] = h; Bl[kb][nt][t][v] = l;
}
__device__ __forceinline__ void bstoreC(unsigned (&Bh)[2][8][33][2], unsigned (&Bl)[2][8][33][2],
                                        int k, int n, float x){
    unsigned h, l; tf32split(x, h, l);
    int kb = k>>3, nt = n>>3, t = (n&7)*4 + (k&3), v = (k>>2)&1;
    Bh[kb][nt][t][v] = h; Bl[kb][nt][t][v] = l;
}

__device__ __forceinline__ void tcomp(const TSmem &S, float (&acc)[4][4][4],
                                      int lane, int wm, int wn)
{
    #pragma unroll
    for (int kb = 0; kb < 2; kb++){
        uint2 bh[4], bl[4];
        #pragma unroll
        for (int j = 0; j < 4; j++){
            int nt = wn*4 + j;
            bh[j] = *(const uint2*)&S.Bh[kb][nt][lane][0];
            bl[j] = *(const uint2*)&S.Bl[kb][nt][lane][0];
        }
        #pragma unroll
        for (int i = 0; i < 4; i++){
            int mt = wm*4 + i;
            uint4 ah = *(const uint4*)&S.Ah[kb][mt][lane][0];
            uint4 al = *(const uint4*)&S.Al[kb][mt][lane][0];
            #pragma unroll
            for (int j = 0; j < 4; j++){
                mma8(acc[i][j], ah, bh[j]);
                mma8(acc[i][j], ah, bl[j]);
                mma8(acc[i][j], al, bh[j]);
            }
        }
    }
}

__device__ __forceinline__ void tcompC(const TSmemC &S, float (&acc)[8][4], int lane, int w)
{
    #pragma unroll
    for (int kb = 0; kb < 2; kb++){
        uint4 ah = *(const uint4*)&S.Ah[kb][w][lane][0];
        uint4 al = *(const uint4*)&S.Al[kb][w][lane][0];
        #pragma unroll
        for (int j = 0; j < 8; j++){
            uint2 bh = *(const uint2*)&S.Bh[kb][j][lane][0];
            uint2 bl = *(const uint2*)&S.Bl[kb][j][lane][0];
            mma8(acc[j], ah, bh);
            mma8(acc[j], ah, bl);
            mma8(acc[j], al, bh);
        }
    }
}

// ---------------- prep ----------------
__global__ void k_prep(const float* __restrict__ W1, const float* __restrict__ W2,
                       const float* __restrict__ V,
                       const float* __restrict__ wih_f, const float* __restrict__ wih_b,
                       const float* __restrict__ bih_f, const float* __restrict__ bhh_f,
                       const float* __restrict__ bih_b, const float* __restrict__ bhh_b,
                       const float* __restrict__ c1w)
{
    int idx = blockIdx.x*blockDim.x + threadIdx.x;
    if (idx < 16384){ int n = idx/128, k = idx%128; g_W1T[k*128+n] = W1[idx]; }
    if (idx < 16384){ int n = idx/128, k = idx%128; g_W2T[k*128+n] = W2[idx]; }
    if (idx < 128*NTF_){ int n = idx/128, k = idx%128; g_VT[k*NTF_+n] = V[idx]; }
    if (idx < 16384){ int g = idx/64, k = idx%64;
        g_WIHT[k*512 + g]       = wih_f[idx];
        g_WIHT[k*512 + 256 + g] = wih_b[idx]; }
    if (idx < 512){ g_biasIH[idx] = (idx < 256) ? (bih_f[idx] + bhh_f[idx])
                                                : (bih_b[idx-256] + bhh_b[idx-256]); }
    if (idx < 32768){ int c = idx/512, k = idx%512; g_c1wT[k*64+c] = c1w[idx]; }
}

// ---------------- conv0 + bn + relu + maxpool4 ----------------
__global__ void __launch_bounds__(256) k_conv0(
    const float* __restrict__ x, const float* __restrict__ w, const float* __restrict__ cb,
    const float* __restrict__ g, const float* __restrict__ bb,
    const float* __restrict__ mm, const float* __restrict__ vv)
{
    __shared__ float4 xs4[1024];
    int b = blockIdx.x, tid = threadIdx.x;
    const float4* in4 = (const float4*)(x + (size_t)b*4096);
    for (int i = tid; i < 1024; i += 256) xs4[i] = in4[i];

    int c = tid & 63;
    float4 wr[8];
    #pragma unroll
    for (int kk = 0; kk < 8; kk++)
        wr[kk] = make_float4(w[c*32 + 0*8 + kk], w[c*32 + 1*8 + kk],
                             w[c*32 + 2*8 + kk], w[c*32 + 3*8 + kk]);
    float scale = g[c] * rsqrtf(vv[c] + 1e-5f);
    float shift = bb[c] - mm[c]*scale;
    float cbc   = cb[c];
    __syncthreads();

    for (int idx = tid; idx < 64*LPOOL; idx += 256){
        int q = idx >> 6;
        float best = -FLT_MAX;
        #pragma unroll
        for (int dp = 0; dp < 4; dp++){
            int p = 4*q + dp;
            float acc = cbc;
            #pragma unroll
            for (int kk = 0; kk < 8; kk++){
                float4 xv = xs4[p+kk];
                acc += wr[kk].x*xv.x + wr[kk].y*xv.y + wr[kk].z*xv.z + wr[kk].w*xv.w;
            }
            best = fmaxf(best, acc*scale + shift);
        }
        g_pooled[(b*64 + c)*LPOOL + q] = fmaxf(best, 0.f);
    }
}

// ---------------- conv1 GEMM (tf32 MMA, pipelined): M=126464, N=64, K=512 ----------------
__global__ void __launch_bounds__(256) k_conv1(
    const float* __restrict__ cb,
    const float* __restrict__ gg, const float* __restrict__ bb,
    const float* __restrict__ mm, const float* __restrict__ vv)
{
    __shared__ TSmemC S;
    int tid = threadIdx.x, lane = tid&31, w = tid>>5;
    int m0  = blockIdx.x*128;
    float acc[8][4];
    #pragma unroll
    for (int j=0;j<8;j++) for (int v=0;v<4;v++) acc[j][v]=0.f;

    int bzl[8], tl[8];
    #pragma unroll
    for (int r = 0; r < 8; r++){
        int i = tid + 256*r;
        int gm = m0 + (i >> 4);
        bzl[r] = gm / T_;
        tl[r]  = gm - bzl[r]*T_;
    }

    float ra[8], rb[4];
    #pragma unroll
    for (int r = 0; r < 8; r++){
        int i = tid + 256*r; int kg = i & 15;
        ra[r] = g_pooled[(bzl[r]*64 + (kg>>3))*LPOOL + tl[r] + (kg&7)];
    }
    #pragma unroll
    for (int r = 0; r < 4; r++){
        int i = tid + 256*r;
        rb[r] = g_c1wT[(i>>6)*64 + (i&63)];
    }
    #pragma unroll
    for (int r = 0; r < 8; r++){ int i = tid + 256*r; astoreT(S.Ah, S.Al, i>>4, i&15, ra[r]); }
    #pragma unroll
    for (int r = 0; r < 4; r++){ int i = tid + 256*r; bstoreC(S.Bh, S.Bl, i>>6, i&63, rb[r]); }
    __syncthreads();

    for (int c = 0; c < 32; c++){
        if (c < 31){
            int k0 = (c+1)*16;
            #pragma unroll
            for (int r = 0; r < 8; r++){
                int i = tid + 256*r; int kg = k0 + (i & 15);
                ra[r] = g_pooled[(bzl[r]*64 + (kg>>3))*LPOOL + tl[r] + (kg&7)];
            }
            #pragma unroll
            for (int r = 0; r < 4; r++){
                int i = tid + 256*r;
                rb[r] = g_c1wT[(k0 + (i>>6))*64 + (i&63)];
            }
        }
        tcompC(S, acc, lane, w);
        __syncthreads();
        if (c < 31){
            #pragma unroll
            for (int r = 0; r < 8; r++){ int i = tid + 256*r; astoreT(S.Ah, S.Al, i>>4, i&15, ra[r]); }
            #pragma unroll
            for (int r = 0; r < 4; r++){ int i = tid + 256*r; bstoreC(S.Bh, S.Bl, i>>6, i&63, rb[r]); }
        }
        __syncthreads();
    }
    int g = lane>>2, tc = lane&3;
    #pragma unroll
    for (int j = 0; j < 8; j++){
        #pragma unroll
        for (int r2 = 0; r2 < 2; r2++){
            int row = m0 + w*16 + g + 8*r2;
            #pragma unroll
            for (int h = 0; h < 2; h++){
                int col = j*8 + tc*2 + h;
                float scale = gg[col] * rsqrtf(vv[col] + 1e-5f);
                float shift = bb[col] + (cb[col] - mm[col])*scale;
                float v = acc[j][r2*2+h];
                g_xlstm[(size_t)row*64 + col] = fmaxf(v*scale + shift, 0.f);
            }
        }
    }
}

// ---------------- xproj GEMM (tf32 MMA, pipelined): M=126464, N=512, K=64 ----------------
__global__ void __launch_bounds__(256) k_xproj()
{
    __shared__ TSmem S;
    int tid = threadIdx.x, lane = tid&31, w = tid>>5, wm = w>>2, wn = w&3;
    int n0 = blockIdx.x*128, m0 = blockIdx.y*128;
    float acc[4][4][4];
    #pragma unroll
    for (int i=0;i<4;i++) for (int j=0;j<4;j++) for (int v=0;v<4;v++) acc[i][j][v]=0.f;

    float ra[8], rb[8];
    #pragma unroll
    for (int r = 0; r < 8; r++){
        int i = tid + 256*r;
        ra[r] = g_xlstm[(size_t)(m0+(i>>4))*64 + (i&15)];
        rb[r] = g_WIHT[(i>>7)*512 + n0 + (i&127)];
    }
    #pragma unroll
    for (int r = 0; r < 8; r++){
        int i = tid + 256*r;
        astoreT(S.Ah, S.Al, i>>4, i&15, ra[r]);
        bstoreT(S.Bh, S.Bl, i>>7, i&127, rb[r]);
    }
    __syncthreads();

    #pragma unroll
    for (int c = 0; c < 4; c++){
        if (c < 3){
            int k0 = (c+1)*16;
            #pragma unroll
            for (int r = 0; r < 8; r++){
                int i = tid + 256*r;
                ra[r] = g_xlstm[(size_t)(m0+(i>>4))*64 + k0 + (i&15)];
                rb[r] = g_WIHT[(k0+(i>>7))*512 + n0 + (i&127)];
            }
        }
        tcomp(S, acc, lane, wm, wn);
        __syncthreads();
        if (c < 3){
            #pragma unroll
            for (int r = 0; r < 8; r++){
                int i = tid + 256*r;
                astoreT(S.Ah, S.Al, i>>4, i&15, ra[r]);
                bstoreT(S.Bh, S.Bl, i>>7, i&127, rb[r]);
            }
        }
        __syncthreads();
    }
    int g = lane>>2, tc = lane&3;
    #pragma unroll
    for (int i=0;i<4;i++)
      #pragma unroll
      for (int j=0;j<4;j++)
        #pragma unroll
        for (int r2=0;r2<2;r2++){
            int row = m0 + wm*64 + i*16 + g + 8*r2;
            int col = n0 + wn*32 + j*8 + tc*2;
            float2 o = make_float2(acc[i][j][r2*2+0] + g_biasIH[col],
                                   acc[i][j][r2*2+1] + g_biasIH[col+1]);
            *(float2*)&g_xproj[(size_t)row*512 + col] = o;
        }
}

// ---------------- LSTM recurrence (persistent, f32x2) ----------------
__global__ void __launch_bounds__(256) k_lstm(const float* __restrict__ whh_f,
                                              const float* __restrict__ whh_b)
{
    __shared__ float hs[64][4];
    __shared__ float g_sm[4][256];
    int dir = blockIdx.x >> 7;
    int b0  = (blockIdx.x & 127) * 4;
    int tid = threadIdx.x;
    const float* whh = dir ? whh_b : whh_f;

    float4 w4[16];
    #pragma unroll
    for (int j4 = 0; j4 < 16; j4++) w4[j4] = *(const float4*)&whh[tid*64 + j4*4];

    hs[tid>>2][tid&3] = 0.f;
    float c = 0.f, hlast = 0.f;

    int tt0 = dir ? 246 : 0;
    float xv[4];
    #pragma unroll
    for (int bi = 0; bi < 4; bi++)
        xv[bi] = g_xproj[((size_t)(b0+bi)*T_ + tt0)*512 + dir*256 + tid];
    __syncthreads();

    for (int s = 0; s < T_; s++){
        u64 acc0 = pack2(xv[0], xv[1]);
        u64 acc1 = pack2(xv[2], xv[3]);

        float xn[4];
        if (s < T_-1){
            int tt2 = dir ? (245 - s) : (s + 1);
            #pragma unroll
            for (int bi = 0; bi < 4; bi++)
                xn[bi] = g_xproj[((size_t)(b0+bi)*T_ + tt2)*512 + dir*256 + tid];
        }

        #pragma unroll
        for (int j4 = 0; j4 < 16; j4++){
            float4 w = w4[j4];
            const ulonglong2* hq = (const ulonglong2*)&hs[j4*4][0];
            ulonglong2 h0 = hq[0];
            ulonglong2 h1 = hq[1];
            ulonglong2 h2 = hq[2];
            ulonglong2 h3 = hq[3];
            u64 wx = pack2(w.x, w.x);
            u64 wy = pack2(w.y, w.y);
            u64 wz = pack2(w.z, w.z);
            u64 ww = pack2(w.w, w.w);
            acc0 = ffma2(wx, h0.x, acc0); acc1 = ffma2(wx, h0.y, acc1);
            acc0 = ffma2(wy, h1.x, acc0); acc1 = ffma2(wy, h1.y, acc1);
            acc0 = ffma2(wz, h2.x, acc0); acc1 = ffma2(wz, h2.y, acc1);
            acc0 = ffma2(ww, h3.x, acc0); acc1 = ffma2(ww, h3.y, acc1);
        }
        float2 f0 = unpack2(acc0), f1 = unpack2(acc1);
        g_sm[0][tid] = f0.x; g_sm[1][tid] = f0.y;
        g_sm[2][tid] = f1.x; g_sm[3][tid] = f1.y;
        __syncthreads();

        int tv = dir ? (246 - s) : s;
        {
            int bi = tid >> 6, j = tid & 63;
            float gi = sigf(g_sm[bi][j]);
            float gf = sigf(g_sm[bi][64+j]);
            float gc = tanhf(g_sm[bi][128+j]);
            float go = sigf(g_sm[bi][192+j]);
            c = gf*c + gi*gc;
            float h = go * tanhf(c);
            hlast = h;
            hs[j][bi] = h;
            g_values[((size_t)(b0+bi)*T_ + tv)*128 + dir*64 + j] = h;
        }
        __syncthreads();
        #pragma unroll
        for (int bi = 0; bi < 4; bi++) xv[bi] = xn[bi];
    }
    {
        int bi = tid >> 6, j = tid & 63;
        g_hT[dir*B_*64 + (b0+bi)*64 + j] = hlast;
    }
}

// ---------------- h_n build + query ----------------
__global__ void k_hnquery(const float* __restrict__ W2b)
{
    __shared__ float hn[128];
    int b = blockIdx.x, j = threadIdx.x;
    int half = j >> 6, jj = j & 63;
    float v;
    if (b < 256) v = g_hT[(2*b + half)*64 + jj];
    else         v = g_hT[B_*64 + (2*(b-256) + half)*64 + jj];
    hn[j] = v;
    __syncthreads();
    float acc = W2b[j];
    #pragma unroll 4
    for (int k = 0; k < 128; k++) acc += hn[k] * g_W2T[k*128 + j];
    g_query[b*128 + j] = acc;
}

// ---------------- keys GEMM + tanh (tf32 MMA, pipelined): M=126464, N=128, K=128 ----------------
__global__ void __launch_bounds__(256) k_keys(const float* __restrict__ W1b)
{
    __shared__ TSmem S;
    int tid = threadIdx.x, lane = tid&31, w = tid>>5, wm = w>>2, wn = w&3;
    int m0 = blockIdx.x*128;
    float acc[4][4][4];
    #pragma unroll
    for (int i=0;i<4;i++) for (int j=0;j<4;j++) for (int v=0;v<4;v++) acc[i][j][v]=0.f;

    float ra[8], rb[8];
    #pragma unroll
    for (int r = 0; r < 8; r++){
        int i = tid + 256*r;
        ra[r] = g_values[(size_t)(m0+(i>>4))*128 + (i&15)];
        rb[r] = g_W1T[(i>>7)*128 + (i&127)];
    }
    #pragma unroll
    for (int r = 0; r < 8; r++){
        int i = tid + 256*r;
        astoreT(S.Ah, S.Al, i>>4, i&15, ra[r]);
        bstoreT(S.Bh, S.Bl, i>>7, i&127, rb[r]);
    }
    __syncthreads();

    #pragma unroll
    for (int c = 0; c < 8; c++){
        if (c < 7){
            int k0 = (c+1)*16;
            #pragma unroll
            for (int r = 0; r < 8; r++){
                int i = tid + 256*r;
                ra[r] = g_values[(size_t)(m0+(i>>4))*128 + k0 + (i&15)];
                rb[r] = g_W1T[(k0+(i>>7))*128 + (i&127)];
            }
        }
        tcomp(S, acc, lane, wm, wn);
        __syncthreads();
        if (c < 7){
            #pragma unroll
            for (int r = 0; r < 8; r++){
                int i = tid + 256*r;
                astoreT(S.Ah, S.Al, i>>4, i&15, ra[r]);
                bstoreT(S.Bh, S.Bl, i>>7, i&127, rb[r]);
            }
        }
        __syncthreads();
    }
    int g = lane>>2, tc = lane&3;
    #pragma unroll
    for (int i=0;i<4;i++)
      #pragma unroll
      for (int j=0;j<4;j++)
        #pragma unroll
        for (int r2=0;r2<2;r2++){
            int row = m0 + wm*64 + i*16 + g + 8*r2;
            int b = row / T_;
            int col = wn*32 + j*8 + tc*2;
            float e0 = tanhf(acc[i][j][r2*2+0] + W1b[col]   + g_query[b*128 + col]);
            float e1 = tanhf(acc[i][j][r2*2+1] + W1b[col+1] + g_query[b*128 + col+1]);
            *(float2*)&g_E[(size_t)row*128 + col] = make_float2(e0, e1);
        }
}

// ---------------- score GEMM (tf32 MMA, pipelined, batched): per b, M=247, N=200, K=128 ----------------
__global__ void __launch_bounds__(256) k_scoreK(const float* __restrict__ Vb)
{
    __shared__ TSmem S;
    int tid = threadIdx.x, lane = tid&31, w = tid>>5, wm = w>>2, wn = w&3;
    int n0 = blockIdx.x*128, m0 = blockIdx.y*128, b = blockIdx.z;
    float acc[4][4][4];
    #pragma unroll
    for (int i=0;i<4;i++) for (int j=0;j<4;j++) for (int v=0;v<4;v++) acc[i][j][v]=0.f;

    float ra[8], rb[8];
    #pragma unroll
    for (int r = 0; r < 8; r++){
        int i = tid + 256*r;
        ra[r] = (m0+(i>>4) < T_) ? g_E[((size_t)b*T_ + m0+(i>>4))*128 + (i&15)] : 0.f;
        rb[r] = (n0+(i&127) < NTF_) ? g_VT[(i>>7)*NTF_ + n0 + (i&127)] : 0.f;
    }
    #pragma unroll
    for (int r = 0; r < 8; r++){
        int i = tid + 256*r;
        astoreT(S.Ah, S.Al, i>>4, i&15, ra[r]);
        bstoreT(S.Bh, S.Bl, i>>7, i&127, rb[r]);
    }
    __syncthreads();

    #pragma unroll
    for (int c = 0; c < 8; c++){
        if (c < 7){
            int k0 = (c+1)*16;
            #pragma unroll
            for (int r = 0; r < 8; r++){
                int i = tid + 256*r;
                ra[r] = (m0+(i>>4) < T_) ? g_E[((size_t)b*T_ + m0+(i>>4))*128 + k0 + (i&15)] : 0.f;
                rb[r] = (n0+(i&127) < NTF_) ? g_VT[(k0+(i>>7))*NTF_ + n0 + (i&127)] : 0.f;
            }
        }
        tcomp(S, acc, lane, wm, wn);
        __syncthreads();
        if (c < 7){
            #pragma unroll
            for (int r = 0; r < 8; r++){
                int i = tid + 256*r;
                astoreT(S.Ah, S.Al, i>>4, i&15, ra[r]);
                bstoreT(S.Bh, S.Bl, i>>7, i&127, rb[r]);
            }
        }
        __syncthreads();
    }
    int g = lane>>2, tc = lane&3;
    #pragma unroll
    for (int i=0;i<4;i++)
      #pragma unroll
      for (int j=0;j<4;j++)
        #pragma unroll
        for (int r2=0;r2<2;r2++){
            int row = m0 + wm*64 + i*16 + g + 8*r2;
            int col = n0 + wn*32 + j*8 + tc*2;
            if (row < T_ && col < NTF_){
                float2 o = make_float2(acc[i][j][r2*2+0] + Vb[col],
                                       acc[i][j][r2*2+1] + Vb[col+1]);
                *(float2*)&g_score[((size_t)b*T_ + row)*NTF_ + col] = o;
            }
        }
}

// ---------------- softmax over time ----------------
__global__ void k_softmax()
{
    int b = blockIdx.x, k = threadIdx.x;
    if (k >= NTF_) return;
    float* base = g_score + (size_t)b*T_*NTF_ + k;
    float m = -FLT_MAX, s = 0.f;
    for (int t = 0; t < T_; t++){
        float x = base[t*NTF_];
        if (x > m){ s = s*__expf(m - x) + 1.f; m = x; }
        else s += __expf(x - m);
    }
    float inv = 1.f / s;
    for (int t = 0; t < T_; t++){
        float x = base[t*NTF_];
        base[t*NTF_] = __expf(x - m) * inv;
    }
}

// ---------------- context GEMM (tf32 MMA, pipelined, batched): per b, M=200, N=128, K=247 ----------------
__global__ void __launch_bounds__(256) k_context()
{
    __shared__ TSmem S;
    int tid = threadIdx.x, lane = tid&31, w = tid>>5, wm = w>>2, wn = w&3;
    int m0 = blockIdx.x*128, b = blockIdx.y;
    float acc[4][4][4];
    #pragma unroll
    for (int i=0;i<4;i++) for (int j=0;j<4;j++) for (int v=0;v<4;v++) acc[i][j][v]=0.f;

    float ra[8], rb[8];
    #pragma unroll
    for (int r = 0; r < 8; r++){
        int i = tid + 256*r; int m = i&127, k = i>>7;
        ra[r] = (m0+m < NTF_) ? g_score[((size_t)b*T_ + k)*NTF_ + m0+m] : 0.f;
        rb[r] = g_values[((size_t)b*T_ + k)*128 + (i&127)];
    }
    #pragma unroll
    for (int r = 0; r < 8; r++){
        int i = tid + 256*r;
        astoreT(S.Ah, S.Al, i&127, i>>7, ra[r]);
        bstoreT(S.Bh, S.Bl, i>>7, i&127, rb[r]);
    }
    __syncthreads();

    for (int c = 0; c < 16; c++){
        if (c < 15){
            int k0 = (c+1)*16;
            #pragma unroll
            for (int r = 0; r < 8; r++){
                int i = tid + 256*r; int m = i&127, k = k0 + (i>>7);
                ra[r] = (k < T_ && m0+m < NTF_) ? g_score[((size_t)b*T_ + k)*NTF_ + m0+m] : 0.f;
                rb[r] = (k < T_) ? g_values[((size_t)b*T_ + k)*128 + (i&127)] : 0.f;
            }
        }
        tcomp(S, acc, lane, wm, wn);
        __syncthreads();
        if (c < 15){
            #pragma unroll
            for (int r = 0; r < 8; r++){
                int i = tid + 256*r;
                astoreT(S.Ah, S.Al, i&127, i>>7, ra[r]);
                bstoreT(S.Bh, S.Bl, i>>7, i&127, rb[r]);
            }
        }
        __syncthreads();
    }
    int g = lane>>2, tc = lane&3;
    #pragma unroll
    for (int i=0;i<4;i++)
      #pragma unroll
      for (int j=0;j<4;j++)
        #pragma unroll
        for (int r2=0;r2<2;r2++){
            int row = m0 + wm*64 + i*16 + g + 8*r2;
            int col = wn*32 + j*8 + tc*2;
            if (row < NTF_){
                float2 o = make_float2(acc[i][j][r2*2+0], acc[i][j][r2*2+1]);
                *(float2*)&g_ctx[((size_t)b*NTF_ + row)*128 + col] = o;
            }
        }
}

// ---------------- per-TF heads ----------------
__global__ void __launch_bounds__(256) k_heads(
    const float* __restrict__ fc1w, const float* __restrict__ fc1b,
    const float* __restrict__ fc2w, const float* __restrict__ fc2b,
    float* __restrict__ out)
{
    __shared__ float fw[128][65];
    __shared__ float cs[16][128];
    __shared__ float red[16][65];
    int tid = threadIdx.x;
    int b0 = blockIdx.x*16, k = blockIdx.y;

    for (int i = tid; i < 8192; i += 256){
        int o = i >> 7, d = i & 127;
        fw[d][o] = fc1w[(size_t)k*8192 + i];
    }
    for (int i = tid; i < 2048; i += 256){
        int bi = i >> 7, d = i & 127;
        cs[bi][d] = g_ctx[((size_t)(b0+bi)*NTF_ + k)*128 + d];
    }
    __syncthreads();

    int o = tid & 63;
    float f1b = fc1b[k*64 + o];
    float f2w = fc2w[k*64 + o];
    #pragma unroll
    for (int p = 0; p < 4; p++){
        int bi = (tid >> 6) + p*4;
        float acc = 0.f;
        #pragma unroll
        for (int d4 = 0; d4 < 32; d4++){
            float4 cv = *(const float4*)&cs[bi][d4*4];
            acc += fw[d4*4+0][o]*cv.x + fw[d4*4+1][o]*cv.y
                 + fw[d4*4+2][o]*cv.z + fw[d4*4+3][o]*cv.w;
        }
        float h1 = fmaxf(acc + f1b, 0.f);
        red[bi][o] = h1 * f2w;
    }
    __syncthreads();
    if (tid < 16){
        float s = fc2b[k];
        #pragma unroll 8
        for (int oo = 0; oo < 64; oo++) s += red[tid][oo];
        out[(size_t)(b0 + tid)*NTF_ + k] = s;
    }
}

// ---------------- launch ----------------
extern "C" void kernel_launch(void* const* d_in, const int* in_sizes, int n_in,
                              void* d_out, int out_size)
{
    const float* DNA    = (const float*)d_in[0];
    const float* c0w    = (const float*)d_in[1];
    const float* c0b    = (const float*)d_in[2];
    const float* bn0g   = (const float*)d_in[3];
    const float* bn0b   = (const float*)d_in[4];
    const float* bn0m   = (const float*)d_in[5];
    const float* bn0v   = (const float*)d_in[6];
    const float* c1w    = (const float*)d_in[7];
    const float* c1b    = (const float*)d_in[8];
    const float* bn1g   = (const float*)d_in[9];
    const float* bn1b   = (const float*)d_in[10];
    const float* bn1m   = (const float*)d_in[11];
    const float* bn1v   = (const float*)d_in[12];
    const float* wih_f  = (const float*)d_in[13];
    const float* whh_f  = (const float*)d_in[14];
    const float* bih_f  = (const float*)d_in[15];
    const float* bhh_f  = (const float*)d_in[16];
    const float* wih_b  = (const float*)d_in[17];
    const float* whh_b  = (const float*)d_in[18];
    const float* bih_b  = (const float*)d_in[19];
    const float* bhh_b  = (const float*)d_in[20];
    const float* W1w    = (const float*)d_in[21];
    const float* W1b    = (const float*)d_in[22];
    const float* W2w    = (const float*)d_in[23];
    const float* W2b    = (const float*)d_in[24];
    const float* Vw     = (const float*)d_in[25];
    const float* Vb     = (const float*)d_in[26];
    const float* fc1w   = (const float*)d_in[27];
    const float* fc1b   = (const float*)d_in[28];
    const float* fc2w   = (const float*)d_in[29];
    const float* fc2b   = (const float*)d_in[30];
    float* out = (float*)d_out;

    k_prep<<<512, 256>>>(W1w, W2w, Vw, wih_f, wih_b, bih_f, bhh_f, bih_b, bhh_b, c1w);
    k_conv0<<<512, 256>>>(DNA, c0w, c0b, bn0g, bn0b, bn0m, bn0v);
    k_conv1<<<988, 256>>>(c1b, bn1g, bn1b, bn1m, bn1v);
    k_xproj<<<dim3(4, 988), 256>>>();
    k_lstm<<<256, 256>>>(whh_f, whh_b);
    k_hnquery<<<512, 128>>>(W2b);
    k_keys<<<988, 256>>>(W1b);
    k_scoreK<<<dim3(2, 2, 512), 256>>>(Vb);
    k_softmax<<<512, 256>>>();
    k_context<<<dim3(2, 512), 256>>>();
    k_heads<<<dim3(32, 200), 256>>>(fc1w, fc1b, fc2w, fc2b, out);
}

// round 10
// speedup vs baseline: 1.5442x; 1.2490x over previous
#include <cuda_runtime.h>
#include <cuda_bf16.h>
#include <math.h>
#include <float.h>

#define B_    512
#define T_    247
#define C_    64
#define NTF_  200
#define LPOOL 254
#define MROWS (B_*T_)      // 126464

typedef unsigned long long u64;

// ---------------- scratch ----------------
__device__ float g_pooled[B_*C_*LPOOL];
__device__ float g_xlstm [MROWS*C_];
__device__ float g_xproj [(size_t)MROWS*512];
__device__ float g_values[MROWS*128];
__device__ float g_hT    [2*B_*64];
__device__ float g_query [B_*128];
__device__ float g_E     [MROWS*128];
__device__ float g_score [MROWS*NTF_];
__device__ float g_ctx   [B_*NTF_*128];
__device__ float g_W1T [128*128];
__device__ float g_W2T [128*128];
__device__ float g_VT  [128*NTF_];
__device__ float g_WIHT[64*512];
__device__ float g_biasIH[512];
__device__ float g_c1wT[512*64];

__device__ __forceinline__ float sigf(float x){ return 1.f/(1.f+__expf(-x)); }

// ---- packed fp32x2 helpers (FFMA2) — lstm ----
__device__ __forceinline__ u64 ffma2(u64 a, u64 b, u64 c){
    u64 d;
    asm("fma.rn.f32x2 %0, %1, %2, %3;" : "=l"(d) : "l"(a), "l"(b), "l"(c));
    return d;
}
__device__ __forceinline__ u64 pack2(float x, float y){
    u64 d;
    asm("mov.b64 %0, {%1, %2};" : "=l"(d) : "f"(x), "f"(y));
    return d;
}
__device__ __forceinline__ float2 unpack2(u64 d){
    float2 f;
    asm("mov.b64 {%0, %1}, %2;" : "=f"(f.x), "=f"(f.y) : "l"(d));
    return f;
}

// ---- bf16 2-term split helpers ----
// pack (x0 -> lo half, x1 -> hi half); residuals likewise
__device__ __forceinline__ void split2(float x0, float x1, unsigned &wh, unsigned &wl){
    unsigned hh;
    asm("cvt.rn.bf16x2.f32 %0, %1, %2;" : "=r"(hh) : "f"(x1), "f"(x0));
    float h0 = __uint_as_float(hh << 16);
    float h1 = __uint_as_float(hh & 0xffff0000u);
    float r0 = x0 - h0, r1 = x1 - h1;
    asm("cvt.rn.bf16x2.f32 %0, %1, %2;" : "=r"(wl) : "f"(r1), "f"(r0));
    wh = hh;
}
__device__ __forceinline__ void mma16(float *d, const uint4 &a, const uint2 &b){
    asm volatile("mma.sync.aligned.m16n8k16.row.col.f32.bf16.bf16.f32 "
        "{%0,%1,%2,%3}, {%4,%5,%6,%7}, {%8,%9}, {%0,%1,%2,%3};"
        : "+f"(d[0]), "+f"(d[1]), "+f"(d[2]), "+f"(d[3])
        : "r"(a.x), "r"(a.y), "r"(a.z), "r"(a.w), "r"(b.x), "r"(b.y));
}

// fragment-permuted smem tiles for one 16-k chunk
struct TSmem {
    unsigned Ah[8][32][4], Al[8][32][4];   // [mtile][lane][reg]
    unsigned Bh[16][33][2], Bl[16][33][2]; // [ntile][lane(+pad)][reg]
};
struct TSmemC {
    unsigned Ah[8][32][4], Al[8][32][4];
    unsigned Bh[8][33][2], Bl[8][33][2];
};

// A[m][2kp],A[m][2kp+1] -> fragment word
__device__ __forceinline__ void astoreB(unsigned (&Ah)[8][32][4], unsigned (&Al)[8][32][4],
                                        int m, int kp, float x0, float x1){
    unsigned wh, wl; split2(x0, x1, wh, wl);
    int mt = m>>4, t = (m&7)*4 + (kp&3);
    int v = ((kp>=4)?2:0) | (((m&15)>=8)?1:0);
    Ah[mt][t][v] = wh; Al[mt][t][v] = wl;
}
// B[2kp][n],B[2kp+1][n] -> fragment word (base pointers, row stride 66 words)
__device__ __forceinline__ void bstoreB(unsigned *Bh, unsigned *Bl,
                                        int kp, int n, float x0, float x1){
    unsigned wh, wl; split2(x0, x1, wh, wl);
    int idx = (n>>3)*66 + ((n&7)*4 + (kp&3))*2 + ((kp>=4)?1:0);
    Bh[idx] = wh; Bl[idx] = wl;
}

__device__ __forceinline__ void tcomp(const TSmem &S, float (&acc)[4][4][4],
                                      int lane, int wm, int wn)
{
    uint2 bh[4], bl[4];
    #pragma unroll
    for (int j = 0; j < 4; j++){
        int nt = wn*4 + j;
        bh[j] = *(const uint2*)&S.Bh[nt][lane][0];
        bl[j] = *(const uint2*)&S.Bl[nt][lane][0];
    }
    #pragma unroll
    for (int i = 0; i < 4; i++){
        int mt = wm*4 + i;
        uint4 ah = *(const uint4*)&S.Ah[mt][lane][0];
        uint4 al = *(const uint4*)&S.Al[mt][lane][0];
        #pragma unroll
        for (int j = 0; j < 4; j++){
            mma16(acc[i][j], ah, bh[j]);
            mma16(acc[i][j], ah, bl[j]);
            mma16(acc[i][j], al, bh[j]);
        }
    }
}

__device__ __forceinline__ void tcompC(const TSmemC &S, float (&acc)[8][4], int lane, int w)
{
    uint4 ah = *(const uint4*)&S.Ah[w][lane][0];
    uint4 al = *(const uint4*)&S.Al[w][lane][0];
    #pragma unroll
    for (int j = 0; j < 8; j++){
        uint2 bh = *(const uint2*)&S.Bh[j][lane][0];
        uint2 bl = *(const uint2*)&S.Bl[j][lane][0];
        mma16(acc[j], ah, bh);
        mma16(acc[j], ah, bl);
        mma16(acc[j], al, bh);
    }
}

// ---------------- prep ----------------
__global__ void k_prep(const float* __restrict__ W1, const float* __restrict__ W2,
                       const float* __restrict__ V,
                       const float* __restrict__ wih_f, const float* __restrict__ wih_b,
                       const float* __restrict__ bih_f, const float* __restrict__ bhh_f,
                       const float* __restrict__ bih_b, const float* __restrict__ bhh_b,
                       const float* __restrict__ c1w)
{
    int idx = blockIdx.x*blockDim.x + threadIdx.x;
    if (idx < 16384){ int n = idx/128, k = idx%128; g_W1T[k*128+n] = W1[idx]; }
    if (idx < 16384){ int n = idx/128, k = idx%128; g_W2T[k*128+n] = W2[idx]; }
    if (idx < 128*NTF_){ int n = idx/128, k = idx%128; g_VT[k*NTF_+n] = V[idx]; }
    if (idx < 16384){ int g = idx/64, k = idx%64;
        g_WIHT[k*512 + g]       = wih_f[idx];
        g_WIHT[k*512 + 256 + g] = wih_b[idx]; }
    if (idx < 512){ g_biasIH[idx] = (idx < 256) ? (bih_f[idx] + bhh_f[idx])
                                                : (bih_b[idx-256] + bhh_b[idx-256]); }
    if (idx < 32768){ int c = idx/512, k = idx%512; g_c1wT[k*64+c] = c1w[idx]; }
}

// ---------------- conv0 + bn + relu + maxpool4 ----------------
__global__ void __launch_bounds__(256) k_conv0(
    const float* __restrict__ x, const float* __restrict__ w, const float* __restrict__ cb,
    const float* __restrict__ g, const float* __restrict__ bb,
    const float* __restrict__ mm, const float* __restrict__ vv)
{
    __shared__ float4 xs4[1024];
    int b = blockIdx.x, tid = threadIdx.x;
    const float4* in4 = (const float4*)(x + (size_t)b*4096);
    for (int i = tid; i < 1024; i += 256) xs4[i] = in4[i];

    int c = tid & 63;
    float4 wr[8];
    #pragma unroll
    for (int kk = 0; kk < 8; kk++)
        wr[kk] = make_float4(w[c*32 + 0*8 + kk], w[c*32 + 1*8 + kk],
                             w[c*32 + 2*8 + kk], w[c*32 + 3*8 + kk]);
    float scale = g[c] * rsqrtf(vv[c] + 1e-5f);
    float shift = bb[c] - mm[c]*scale;
    float cbc   = cb[c];
    __syncthreads();

    for (int idx = tid; idx < 64*LPOOL; idx += 256){
        int q = idx >> 6;
        float best = -FLT_MAX;
        #pragma unroll
        for (int dp = 0; dp < 4; dp++){
            int p = 4*q + dp;
            float acc = cbc;
            #pragma unroll
            for (int kk = 0; kk < 8; kk++){
                float4 xv = xs4[p+kk];
                acc += wr[kk].x*xv.x + wr[kk].y*xv.y + wr[kk].z*xv.z + wr[kk].w*xv.w;
            }
            best = fmaxf(best, acc*scale + shift);
        }
        g_pooled[(b*64 + c)*LPOOL + q] = fmaxf(best, 0.f);
    }
}

// ---------------- conv1 GEMM (bf16 split MMA): M=126464, N=64, K=512 ----------------
__global__ void __launch_bounds__(256) k_conv1(
    const float* __restrict__ cb,
    const float* __restrict__ gg, const float* __restrict__ bb,
    const float* __restrict__ mm, const float* __restrict__ vv)
{
    __shared__ TSmemC S;
    int tid = threadIdx.x, lane = tid&31, w = tid>>5;
    int m0  = blockIdx.x*128;
    float acc[8][4];
    #pragma unroll
    for (int j=0;j<8;j++) for (int v=0;v<4;v++) acc[j][v]=0.f;

    int mA = tid>>3, kpA = tid&7;     // A: m = mA+32r, kp = kpA
    int bz[4], tl[4];
    #pragma unroll
    for (int r = 0; r < 4; r++){
        int gm = m0 + mA + 32*r;
        bz[r] = gm / T_;
        tl[r] = gm - bz[r]*T_;
    }

    float ax0[4], ax1[4], bx0[2], bx1[2];
    // prologue load chunk 0
    {
        int k = 2*kpA;
        #pragma unroll
        for (int r = 0; r < 4; r++){
            int base = (bz[r]*64 + (k>>3))*LPOOL + tl[r] + (k&7);
            ax0[r] = g_pooled[base]; ax1[r] = g_pooled[base+1];
        }
        #pragma unroll
        for (int r = 0; r < 2; r++){
            int i = tid + 256*r; int n = i&63, kp = (i>>6)&7;
            bx0[r] = g_c1wT[(2*kp)*64 + n];
            bx1[r] = g_c1wT[(2*kp+1)*64 + n];
        }
        #pragma unroll
        for (int r = 0; r < 4; r++) astoreB(S.Ah, S.Al, mA+32*r, kpA, ax0[r], ax1[r]);
        #pragma unroll
        for (int r = 0; r < 2; r++){
            int i = tid + 256*r; int n = i&63, kp = (i>>6)&7;
            bstoreB(&S.Bh[0][0][0], &S.Bl[0][0][0], kp, n, bx0[r], bx1[r]);
        }
    }
    __syncthreads();

    for (int c = 0; c < 32; c++){
        if (c < 31){
            int k0 = (c+1)*16;
            int k = k0 + 2*kpA;
            #pragma unroll
            for (int r = 0; r < 4; r++){
                int base = (bz[r]*64 + (k>>3))*LPOOL + tl[r] + (k&7);
                ax0[r] = g_pooled[base]; ax1[r] = g_pooled[base+1];
            }
            #pragma unroll
            for (int r = 0; r < 2; r++){
                int i = tid + 256*r; int n = i&63, kp = (i>>6)&7;
                bx0[r] = g_c1wT[(k0+2*kp)*64 + n];
                bx1[r] = g_c1wT[(k0+2*kp+1)*64 + n];
            }
        }
        tcompC(S, acc, lane, w);
        __syncthreads();
        if (c < 31){
            #pragma unroll
            for (int r = 0; r < 4; r++) astoreB(S.Ah, S.Al, mA+32*r, kpA, ax0[r], ax1[r]);
            #pragma unroll
            for (int r = 0; r < 2; r++){
                int i = tid + 256*r; int n = i&63, kp = (i>>6)&7;
                bstoreB(&S.Bh[0][0][0], &S.Bl[0][0][0], kp, n, bx0[r], bx1[r]);
            }
        }
        __syncthreads();
    }
    int g = lane>>2, tc = lane&3;
    #pragma unroll
    for (int j = 0; j < 8; j++){
        #pragma unroll
        for (int r2 = 0; r2 < 2; r2++){
            int row = m0 + w*16 + g + 8*r2;
            #pragma unroll
            for (int h = 0; h < 2; h++){
                int col = j*8 + tc*2 + h;
                float scale = gg[col] * rsqrtf(vv[col] + 1e-5f);
                float shift = bb[col] + (cb[col] - mm[col])*scale;
                float v = acc[j][r2*2+h];
                g_xlstm[(size_t)row*64 + col] = fmaxf(v*scale + shift, 0.f);
            }
        }
    }
}

// ---------------- xproj GEMM (bf16 split MMA): M=126464, N=512, K=64 ----------------
__global__ void __launch_bounds__(256) k_xproj()
{
    __shared__ TSmem S;
    int tid = threadIdx.x, lane = tid&31, w = tid>>5, wm = w>>2, wn = w&3;
    int n0 = blockIdx.x*128, m0 = blockIdx.y*128;
    float acc[4][4][4];
    #pragma unroll
    for (int i=0;i<4;i++) for (int j=0;j<4;j++) for (int v=0;v<4;v++) acc[i][j][v]=0.f;

    int mA = tid>>3, kpA = tid&7;     // A positions
    int kpB = tid>>5, nB = tid&31;    // B positions: n = nB+32r

    float2 ra[4]; float bx0[4], bx1[4];
    {
        #pragma unroll
        for (int r = 0; r < 4; r++)
            ra[r] = *(const float2*)&g_xlstm[(size_t)(m0+mA+32*r)*64 + 2*kpA];
        #pragma unroll
        for (int r = 0; r < 4; r++){
            int n = nB + 32*r;
            bx0[r] = g_WIHT[(2*kpB)*512 + n0 + n];
            bx1[r] = g_WIHT[(2*kpB+1)*512 + n0 + n];
        }
        #pragma unroll
        for (int r = 0; r < 4; r++) astoreB(S.Ah, S.Al, mA+32*r, kpA, ra[r].x, ra[r].y);
        #pragma unroll
        for (int r = 0; r < 4; r++)
            bstoreB(&S.Bh[0][0][0], &S.Bl[0][0][0], kpB, nB+32*r, bx0[r], bx1[r]);
    }
    __syncthreads();

    #pragma unroll
    for (int c = 0; c < 4; c++){
        if (c < 3){
            int k0 = (c+1)*16;
            #pragma unroll
            for (int r = 0; r < 4; r++)
                ra[r] = *(const float2*)&g_xlstm[(size_t)(m0+mA+32*r)*64 + k0 + 2*kpA];
            #pragma unroll
            for (int r = 0; r < 4; r++){
                int n = nB + 32*r;
                bx0[r] = g_WIHT[(k0+2*kpB)*512 + n0 + n];
                bx1[r] = g_WIHT[(k0+2*kpB+1)*512 + n0 + n];
            }
        }
        tcomp(S, acc, lane, wm, wn);
        __syncthreads();
        if (c < 3){
            #pragma unroll
            for (int r = 0; r < 4; r++) astoreB(S.Ah, S.Al, mA+32*r, kpA, ra[r].x, ra[r].y);
            #pragma unroll
            for (int r = 0; r < 4; r++)
                bstoreB(&S.Bh[0][0][0], &S.Bl[0][0][0], kpB, nB+32*r, bx0[r], bx1[r]);
        }
        __syncthreads();
    }
    int g = lane>>2, tc = lane&3;
    #pragma unroll
    for (int i=0;i<4;i++)
      #pragma unroll
      for (int j=0;j<4;j++)
        #pragma unroll
        for (int r2=0;r2<2;r2++){
            int row = m0 + wm*64 + i*16 + g + 8*r2;
            int col = n0 + wn*32 + j*8 + tc*2;
            float2 o = make_float2(acc[i][j][r2*2+0] + g_biasIH[col],
                                   acc[i][j][r2*2+1] + g_biasIH[col+1]);
            *(float2*)&g_xproj[(size_t)row*512 + col] = o;
        }
}

// ---------------- LSTM recurrence (persistent, f32x2) ----------------
__global__ void __launch_bounds__(256) k_lstm(const float* __restrict__ whh_f,
                                              const float* __restrict__ whh_b)
{
    __shared__ float hs[64][4];
    __shared__ float g_sm[4][256];
    int dir = blockIdx.x >> 7;
    int b0  = (blockIdx.x & 127) * 4;
    int tid = threadIdx.x;
    const float* whh = dir ? whh_b : whh_f;

    float4 w4[16];
    #pragma unroll
    for (int j4 = 0; j4 < 16; j4++) w4[j4] = *(const float4*)&whh[tid*64 + j4*4];

    hs[tid>>2][tid&3] = 0.f;
    float c = 0.f, hlast = 0.f;

    int tt0 = dir ? 246 : 0;
    float xv[4];
    #pragma unroll
    for (int bi = 0; bi < 4; bi++)
        xv[bi] = g_xproj[((size_t)(b0+bi)*T_ + tt0)*512 + dir*256 + tid];
    __syncthreads();

    for (int s = 0; s < T_; s++){
        u64 acc0 = pack2(xv[0], xv[1]);
        u64 acc1 = pack2(xv[2], xv[3]);

        float xn[4];
        if (s < T_-1){
            int tt2 = dir ? (245 - s) : (s + 1);
            #pragma unroll
            for (int bi = 0; bi < 4; bi++)
                xn[bi] = g_xproj[((size_t)(b0+bi)*T_ + tt2)*512 + dir*256 + tid];
        }

        #pragma unroll
        for (int j4 = 0; j4 < 16; j4++){
            float4 w = w4[j4];
            const ulonglong2* hq = (const ulonglong2*)&hs[j4*4][0];
            ulonglong2 h0 = hq[0];
            ulonglong2 h1 = hq[1];
            ulonglong2 h2 = hq[2];
            ulonglong2 h3 = hq[3];
            u64 wx = pack2(w.x, w.x);
            u64 wy = pack2(w.y, w.y);
            u64 wz = pack2(w.z, w.z);
            u64 ww = pack2(w.w, w.w);
            acc0 = ffma2(wx, h0.x, acc0); acc1 = ffma2(wx, h0.y, acc1);
            acc0 = ffma2(wy, h1.x, acc0); acc1 = ffma2(wy, h1.y, acc1);
            acc0 = ffma2(wz, h2.x, acc0); acc1 = ffma2(wz, h2.y, acc1);
            acc0 = ffma2(ww, h3.x, acc0); acc1 = ffma2(ww, h3.y, acc1);
        }
        float2 f0 = unpack2(acc0), f1 = unpack2(acc1);
        g_sm[0][tid] = f0.x; g_sm[1][tid] = f0.y;
        g_sm[2][tid] = f1.x; g_sm[3][tid] = f1.y;
        __syncthreads();

        int tv = dir ? (246 - s) : s;
        {
            int bi = tid >> 6, j = tid & 63;
            float gi = sigf(g_sm[bi][j]);
            float gf = sigf(g_sm[bi][64+j]);
            float gc = tanhf(g_sm[bi][128+j]);
            float go = sigf(g_sm[bi][192+j]);
            c = gf*c + gi*gc;
            float h = go * tanhf(c);
            hlast = h;
            hs[j][bi] = h;
            g_values[((size_t)(b0+bi)*T_ + tv)*128 + dir*64 + j] = h;
        }
        __syncthreads();
        #pragma unroll
        for (int bi = 0; bi < 4; bi++) xv[bi] = xn[bi];
    }
    {
        int bi = tid >> 6, j = tid & 63;
        g_hT[dir*B_*64 + (b0+bi)*64 + j] = hlast;
    }
}

// ---------------- h_n build + query ----------------
__global__ void k_hnquery(const float* __restrict__ W2b)
{
    __shared__ float hn[128];
    int b = blockIdx.x, j = threadIdx.x;
    int half = j >> 6, jj = j & 63;
    float v;
    if (b < 256) v = g_hT[(2*b + half)*64 + jj];
    else         v = g_hT[B_*64 + (2*(b-256) + half)*64 + jj];
    hn[j] = v;
    __syncthreads();
    float acc = W2b[j];
    #pragma unroll 4
    for (int k = 0; k < 128; k++) acc += hn[k] * g_W2T[k*128 + j];
    g_query[b*128 + j] = acc;
}

// ---------------- keys GEMM + tanh (bf16 split MMA): M=126464, N=128, K=128 ----------------
__global__ void __launch_bounds__(256) k_keys(const float* __restrict__ W1b)
{
    __shared__ TSmem S;
    int tid = threadIdx.x, lane = tid&31, w = tid>>5, wm = w>>2, wn = w&3;
    int m0 = blockIdx.x*128;
    float acc[4][4][4];
    #pragma unroll
    for (int i=0;i<4;i++) for (int j=0;j<4;j++) for (int v=0;v<4;v++) acc[i][j][v]=0.f;

    int mA = tid>>3, kpA = tid&7;
    int kpB = tid>>5, nB = tid&31;

    float2 ra[4]; float bx0[4], bx1[4];
    {
        #pragma unroll
        for (int r = 0; r < 4; r++)
            ra[r] = *(const float2*)&g_values[(size_t)(m0+mA+32*r)*128 + 2*kpA];
        #pragma unroll
        for (int r = 0; r < 4; r++){
            int n = nB + 32*r;
            bx0[r] = g_W1T[(2*kpB)*128 + n];
            bx1[r] = g_W1T[(2*kpB+1)*128 + n];
        }
        #pragma unroll
        for (int r = 0; r < 4; r++) astoreB(S.Ah, S.Al, mA+32*r, kpA, ra[r].x, ra[r].y);
        #pragma unroll
        for (int r = 0; r < 4; r++)
            bstoreB(&S.Bh[0][0][0], &S.Bl[0][0][0], kpB, nB+32*r, bx0[r], bx1[r]);
    }
    __syncthreads();

    #pragma unroll
    for (int c = 0; c < 8; c++){
        if (c < 7){
            int k0 = (c+1)*16;
            #pragma unroll
            for (int r = 0; r < 4; r++)
                ra[r] = *(const float2*)&g_values[(size_t)(m0+mA+32*r)*128 + k0 + 2*kpA];
            #pragma unroll
            for (int r = 0; r < 4; r++){
                int n = nB + 32*r;
                bx0[r] = g_W1T[(k0+2*kpB)*128 + n];
                bx1[r] = g_W1T[(k0+2*kpB+1)*128 + n];
            }
        }
        tcomp(S, acc, lane, wm, wn);
        __syncthreads();
        if (c < 7){
            #pragma unroll
            for (int r = 0; r < 4; r++) astoreB(S.Ah, S.Al, mA+32*r, kpA, ra[r].x, ra[r].y);
            #pragma unroll
            for (int r = 0; r < 4; r++)
                bstoreB(&S.Bh[0][0][0], &S.Bl[0][0][0], kpB, nB+32*r, bx0[r], bx1[r]);
        }
        __syncthreads();
    }
    int g = lane>>2, tc = lane&3;
    #pragma unroll
    for (int i=0;i<4;i++)
      #pragma unroll
      for (int j=0;j<4;j++)
        #pragma unroll
        for (int r2=0;r2<2;r2++){
            int row = m0 + wm*64 + i*16 + g + 8*r2;
            int b = row / T_;
            int col = wn*32 + j*8 + tc*2;
            float e0 = tanhf(acc[i][j][r2*2+0] + W1b[col]   + g_query[b*128 + col]);
            float e1 = tanhf(acc[i][j][r2*2+1] + W1b[col+1] + g_query[b*128 + col+1]);
            *(float2*)&g_E[(size_t)row*128 + col] = make_float2(e0, e1);
        }
}

// ---------------- score GEMM (bf16 split MMA, batched): per b, M=247, N=200, K=128 ----------------
__global__ void __launch_bounds__(256) k_scoreK(const float* __restrict__ Vb)
{
    __shared__ TSmem S;
    int tid = threadIdx.x, lane = tid&31, w = tid>>5, wm = w>>2, wn = w&3;
    int n0 = blockIdx.x*128, m0 = blockIdx.y*128, b = blockIdx.z;
    float acc[4][4][4];
    #pragma unroll
    for (int i=0;i<4;i++) for (int j=0;j<4;j++) for (int v=0;v<4;v++) acc[i][j][v]=0.f;

    int mA = tid>>3, kpA = tid&7;
    int kpB = tid>>5, nB = tid&31;

    float2 ra[4]; float bx0[4], bx1[4];
    {
        #pragma unroll
        for (int r = 0; r < 4; r++){
            int m = mA + 32*r;
            ra[r] = (m0+m < T_) ? *(const float2*)&g_E[((size_t)b*T_ + m0+m)*128 + 2*kpA]
                                : make_float2(0.f, 0.f);
        }
        #pragma unroll
        for (int r = 0; r < 4; r++){
            int n = nB + 32*r;
            bool ok = (n0+n < NTF_);
            bx0[r] = ok ? g_VT[(2*kpB)*NTF_ + n0+n] : 0.f;
            bx1[r] = ok ? g_VT[(2*kpB+1)*NTF_ + n0+n] : 0.f;
        }
        #pragma unroll
        for (int r = 0; r < 4; r++) astoreB(S.Ah, S.Al, mA+32*r, kpA, ra[r].x, ra[r].y);
        #pragma unroll
        for (int r = 0; r < 4; r++)
            bstoreB(&S.Bh[0][0][0], &S.Bl[0][0][0], kpB, nB+32*r, bx0[r], bx1[r]);
    }
    __syncthreads();

    #pragma unroll
    for (int c = 0; c < 8; c++){
        if (c < 7){
            int k0 = (c+1)*16;
            #pragma unroll
            for (int r = 0; r < 4; r++){
                int m = mA + 32*r;
                ra[r] = (m0+m < T_) ? *(const float2*)&g_E[((size_t)b*T_ + m0+m)*128 + k0 + 2*kpA]
                                    : make_float2(0.f, 0.f);
            }
            #pragma unroll
            for (int r = 0; r < 4; r++){
                int n = nB + 32*r;
                bool ok = (n0+n < NTF_);
                bx0[r] = ok ? g_VT[(k0+2*kpB)*NTF_ + n0+n] : 0.f;
                bx1[r] = ok ? g_VT[(k0+2*kpB+1)*NTF_ + n0+n] : 0.f;
            }
        }
        tcomp(S, acc, lane, wm, wn);
        __syncthreads();
        if (c < 7){
            #pragma unroll
            for (int r = 0; r < 4; r++) astoreB(S.Ah, S.Al, mA+32*r, kpA, ra[r].x, ra[r].y);
            #pragma unroll
            for (int r = 0; r < 4; r++)
                bstoreB(&S.Bh[0][0][0], &S.Bl[0][0][0], kpB, nB+32*r, bx0[r], bx1[r]);
        }
        __syncthreads();
    }
    int g = lane>>2, tc = lane&3;
    #pragma unroll
    for (int i=0;i<4;i++)
      #pragma unroll
      for (int j=0;j<4;j++)
        #pragma unroll
        for (int r2=0;r2<2;r2++){
            int row = m0 + wm*64 + i*16 + g + 8*r2;
            int col = n0 + wn*32 + j*8 + tc*2;
            if (row < T_ && col < NTF_){
                float2 o = make_float2(acc[i][j][r2*2+0] + Vb[col],
                                       acc[i][j][r2*2+1] + Vb[col+1]);
                *(float2*)&g_score[((size_t)b*T_ + row)*NTF_ + col] = o;
            }
        }
}

// ---------------- softmax over time ----------------
__global__ void k_softmax()
{
    int b = blockIdx.x, k = threadIdx.x;
    if (k >= NTF_) return;
    float* base = g_score + (size_t)b*T_*NTF_ + k;
    float m = -FLT_MAX, s = 0.f;
    for (int t = 0; t < T_; t++){
        float x = base[t*NTF_];
        if (x > m){ s = s*__expf(m - x) + 1.f; m = x; }
        else s += __expf(x - m);
    }
    float inv = 1.f / s;
    for (int t = 0; t < T_; t++){
        float x = base[t*NTF_];
        base[t*NTF_] = __expf(x - m) * inv;
    }
}

// ---------------- context GEMM (bf16 split MMA, batched): per b, M=200, N=128, K=247 ----------------
__global__ void __launch_bounds__(256) k_context()
{
    __shared__ TSmem S;
    int tid = threadIdx.x, lane = tid&31, w = tid>>5, wm = w>>2, wn = w&3;
    int m0 = blockIdx.x*128, b = blockIdx.y;
    float acc[4][4][4];
    #pragma unroll
    for (int i=0;i<4;i++) for (int j=0;j<4;j++) for (int v=0;v<4;v++) acc[i][j][v]=0.f;

    // A = score^T (m = TF dim, k = time); coalesced: m = mB+32r, kp = kpB
    int kpB = tid>>5, mB = tid&31;

    float ax0[4], ax1[4], bx0[4], bx1[4];
    {
        #pragma unroll
        for (int r = 0; r < 4; r++){
            int m = mB + 32*r;
            bool okm = (m0+m < NTF_);
            int t0 = 2*kpB, t1 = 2*kpB+1;
            ax0[r] = (okm && t0 < T_) ? g_score[((size_t)b*T_ + t0)*NTF_ + m0+m] : 0.f;
            ax1[r] = (okm && t1 < T_) ? g_score[((size_t)b*T_ + t1)*NTF_ + m0+m] : 0.f;
            bx0[r] = (t0 < T_) ? g_values[((size_t)b*T_ + t0)*128 + m] : 0.f;
            bx1[r] = (t1 < T_) ? g_values[((size_t)b*T_ + t1)*128 + m] : 0.f;
        }
        #pragma unroll
        for (int r = 0; r < 4; r++){
            astoreB(S.Ah, S.Al, mB+32*r, kpB, ax0[r], ax1[r]);
            bstoreB(&S.Bh[0][0][0], &S.Bl[0][0][0], kpB, mB+32*r, bx0[r], bx1[r]);
        }
    }
    __syncthreads();

    for (int c = 0; c < 16; c++){
        if (c < 15){
            int k0 = (c+1)*16;
            #pragma unroll
            for (int r = 0; r < 4; r++){
                int m = mB + 32*r;
                bool okm = (m0+m < NTF_);
                int t0 = k0 + 2*kpB, t1 = t0 + 1;
                ax0[r] = (okm && t0 < T_) ? g_score[((size_t)b*T_ + t0)*NTF_ + m0+m] : 0.f;
                ax1[r] = (okm && t1 < T_) ? g_score[((size_t)b*T_ + t1)*NTF_ + m0+m] : 0.f;
                bx0[r] = (t0 < T_) ? g_values[((size_t)b*T_ + t0)*128 + m] : 0.f;
                bx1[r] = (t1 < T_) ? g_values[((size_t)b*T_ + t1)*128 + m] : 0.f;
            }
        }
        tcomp(S, acc, lane, wm, wn);
        __syncthreads();
        if (c < 15){
            #pragma unroll
            for (int r = 0; r < 4; r++){
                astoreB(S.Ah, S.Al, mB+32*r, kpB, ax0[r], ax1[r]);
                bstoreB(&S.Bh[0][0][0], &S.Bl[0][0][0], kpB, mB+32*r, bx0[r], bx1[r]);
            }
        }
        __syncthreads();
    }
    int g = lane>>2, tc = lane&3;
    #pragma unroll
    for (int i=0;i<4;i++)
      #pragma unroll
      for (int j=0;j<4;j++)
        #pragma unroll
        for (int r2=0;r2<2;r2++){
            int row = m0 + wm*64 + i*16 + g + 8*r2;
            int col = wn*32 + j*8 + tc*2;
            if (row < NTF_){
                float2 o = make_float2(acc[i][j][r2*2+0], acc[i][j][r2*2+1]);
                *(float2*)&g_ctx[((size_t)b*NTF_ + row)*128 + col] = o;
            }
        }
}

// ---------------- per-TF heads ----------------
__global__ void __launch_bounds__(256) k_heads(
    const float* __restrict__ fc1w, const float* __restrict__ fc1b,
    const float* __restrict__ fc2w, const float* __restrict__ fc2b,
    float* __restrict__ out)
{
    __shared__ float fw[128][65];
    __shared__ float cs[16][128];
    __shared__ float red[16][65];
    int tid = threadIdx.x;
    int b0 = blockIdx.x*16, k = blockIdx.y;

    for (int i = tid; i < 8192; i += 256){
        int o = i >> 7, d = i & 127;
        fw[d][o] = fc1w[(size_t)k*8192 + i];
    }
    for (int i = tid; i < 2048; i += 256){
        int bi = i >> 7, d = i & 127;
        cs[bi][d] = g_ctx[((size_t)(b0+bi)*NTF_ + k)*128 + d];
    }
    __syncthreads();

    int o = tid & 63;
    float f1b = fc1b[k*64 + o];
    float f2w = fc2w[k*64 + o];
    #pragma unroll
    for (int p = 0; p < 4; p++){
        int bi = (tid >> 6) + p*4;
        float acc = 0.f;
        #pragma unroll
        for (int d4 = 0; d4 < 32; d4++){
            float4 cv = *(const float4*)&cs[bi][d4*4];
            acc += fw[d4*4+0][o]*cv.x + fw[d4*4+1][o]*cv.y
                 + fw[d4*4+2][o]*cv.z + fw[d4*4+3][o]*cv.w;
        }
        float h1 = fmaxf(acc + f1b, 0.f);
        red[bi][o] = h1 * f2w;
    }
    __syncthreads();
    if (tid < 16){
        float s = fc2b[k];
        #pragma unroll 8
        for (int oo = 0; oo < 64; oo++) s += red[tid][oo];
        out[(size_t)(b0 + tid)*NTF_ + k] = s;
    }
}

// ---------------- launch ----------------
extern "C" void kernel_launch(void* const* d_in, const int* in_sizes, int n_in,
                              void* d_out, int out_size)
{
    const float* DNA    = (const float*)d_in[0];
    const float* c0w    = (const float*)d_in[1];
    const float* c0b    = (const float*)d_in[2];
    const float* bn0g   = (const float*)d_in[3];
    const float* bn0b   = (const float*)d_in[4];
    const float* bn0m   = (const float*)d_in[5];
    const float* bn0v   = (const float*)d_in[6];
    const float* c1w    = (const float*)d_in[7];
    const float* c1b    = (const float*)d_in[8];
    const float* bn1g   = (const float*)d_in[9];
    const float* bn1b   = (const float*)d_in[10];
    const float* bn1m   = (const float*)d_in[11];
    const float* bn1v   = (const float*)d_in[12];
    const float* wih_f  = (const float*)d_in[13];
    const float* whh_f  = (const float*)d_in[14];
    const float* bih_f  = (const float*)d_in[15];
    const float* bhh_f  = (const float*)d_in[16];
    const float* wih_b  = (const float*)d_in[17];
    const float* whh_b  = (const float*)d_in[18];
    const float* bih_b  = (const float*)d_in[19];
    const float* bhh_b  = (const float*)d_in[20];
    const float* W1w    = (const float*)d_in[21];
    const float* W1b    = (const float*)d_in[22];
    const float* W2w    = (const float*)d_in[23];
    const float* W2b    = (const float*)d_in[24];
    const float* Vw     = (const float*)d_in[25];
    const float* Vb     = (const float*)d_in[26];
    const float* fc1w   = (const float*)d_in[27];
    const float* fc1b   = (const float*)d_in[28];
    const float* fc2w   = (const float*)d_in[29];
    const float* fc2b   = (const float*)d_in[30];
    float* out = (float*)d_out;

    k_prep<<<512, 256>>>(W1w, W2w, Vw, wih_f, wih_b, bih_f, bhh_f, bih_b, bhh_b, c1w);
    k_conv0<<<512, 256>>>(DNA, c0w, c0b, bn0g, bn0b, bn0m, bn0v);
    k_conv1<<<988, 256>>>(c1b, bn1g, bn1b, bn1m, bn1v);
    k_xproj<<<dim3(4, 988), 256>>>();
    k_lstm<<<256, 256>>>(whh_f, whh_b);
    k_hnquery<<<512, 128>>>(W2b);
    k_keys<<<988, 256>>>(W1b);
    k_scoreK<<<dim3(2, 2, 512), 256>>>(Vb);
    k_softmax<<<512, 256>>>();
    k_context<<<dim3(2, 512), 256>>>();
    k_heads<<<dim3(32, 200), 256>>>(fc1w, fc1b, fc2w, fc2b, out);
}

// round 11
// speedup vs baseline: 1.6215x; 1.0501x over previous
#include <cuda_runtime.h>
#include <cuda_bf16.h>
#include <math.h>
#include <float.h>

#define B_    512
#define T_    247
#define C_    64
#define NTF_  200
#define LPOOL 254
#define MROWS (B_*T_)      // 126464

typedef unsigned long long u64;

// ---------------- scratch ----------------
__device__ float g_pooled[B_*C_*LPOOL];
__device__ float g_xlstm [MROWS*C_];
__device__ float g_xproj [(size_t)MROWS*512];
__device__ float g_values[MROWS*128];
__device__ float g_hT    [2*B_*64];
__device__ float g_query [B_*128];
__device__ float g_E     [MROWS*128];
__device__ float g_score [MROWS*NTF_];
__device__ float g_ctx   [B_*NTF_*128];
__device__ float g_W1T [128*128];
__device__ float g_W2T [128*128];
__device__ float g_VT  [128*NTF_];
__device__ float g_WIHT[64*512];
__device__ float g_biasIH[512];
__device__ float g_c1wT[512*64];

__device__ __forceinline__ float sigf(float x){ return 1.f/(1.f+__expf(-x)); }

// ---- packed fp32x2 helpers (FFMA2) — lstm ----
__device__ __forceinline__ u64 ffma2(u64 a, u64 b, u64 c){
    u64 d;
    asm("fma.rn.f32x2 %0, %1, %2, %3;" : "=l"(d) : "l"(a), "l"(b), "l"(c));
    return d;
}
__device__ __forceinline__ u64 pack2(float x, float y){
    u64 d;
    asm("mov.b64 %0, {%1, %2};" : "=l"(d) : "f"(x), "f"(y));
    return d;
}
__device__ __forceinline__ float2 unpack2(u64 d){
    float2 f;
    asm("mov.b64 {%0, %1}, %2;" : "=f"(f.x), "=f"(f.y) : "l"(d));
    return f;
}

// ---- bf16 2-term split helpers ----
__device__ __forceinline__ void split2(float x0, float x1, unsigned &wh, unsigned &wl){
    unsigned hh;
    asm("cvt.rn.bf16x2.f32 %0, %1, %2;" : "=r"(hh) : "f"(x1), "f"(x0));
    float h0 = __uint_as_float(hh << 16);
    float h1 = __uint_as_float(hh & 0xffff0000u);
    float r0 = x0 - h0, r1 = x1 - h1;
    asm("cvt.rn.bf16x2.f32 %0, %1, %2;" : "=r"(wl) : "f"(r1), "f"(r0));
    wh = hh;
}
__device__ __forceinline__ void mma16(float *d, const uint4 &a, const uint2 &b){
    asm volatile("mma.sync.aligned.m16n8k16.row.col.f32.bf16.bf16.f32 "
        "{%0,%1,%2,%3}, {%4,%5,%6,%7}, {%8,%9}, {%0,%1,%2,%3};"
        : "+f"(d[0]), "+f"(d[1]), "+f"(d[2]), "+f"(d[3])
        : "r"(a.x), "r"(a.y), "r"(a.z), "r"(a.w), "r"(b.x), "r"(b.y));
}

// fragment-permuted smem tiles for one 16-k chunk
struct TSmem {
    unsigned Ah[8][32][4], Al[8][32][4];   // [mtile][lane][reg]
    unsigned Bh[16][33][2], Bl[16][33][2]; // [ntile][lane(+pad)][reg]
};
struct TSmemC {
    unsigned Ah[8][32][4], Al[8][32][4];
    unsigned Bh[8][33][2], Bl[8][33][2];
};

__device__ __forceinline__ void astoreB(unsigned (&Ah)[8][32][4], unsigned (&Al)[8][32][4],
                                        int m, int kp, float x0, float x1){
    unsigned wh, wl; split2(x0, x1, wh, wl);
    int mt = m>>4, t = (m&7)*4 + (kp&3);
    int v = ((kp>=4)?2:0) | (((m&15)>=8)?1:0);
    Ah[mt][t][v] = wh; Al[mt][t][v] = wl;
}
__device__ __forceinline__ void bstoreB(unsigned *Bh, unsigned *Bl,
                                        int kp, int n, float x0, float x1){
    unsigned wh, wl; split2(x0, x1, wh, wl);
    int idx = (n>>3)*66 + ((n&7)*4 + (kp&3))*2 + ((kp>=4)?1:0);
    Bh[idx] = wh; Bl[idx] = wl;
}

__device__ __forceinline__ void tcomp(const TSmem &S, float (&acc)[4][4][4],
                                      int lane, int wm, int wn)
{
    uint2 bh[4], bl[4];
    #pragma unroll
    for (int j = 0; j < 4; j++){
        int nt = wn*4 + j;
        bh[j] = *(const uint2*)&S.Bh[nt][lane][0];
        bl[j] = *(const uint2*)&S.Bl[nt][lane][0];
    }
    #pragma unroll
    for (int i = 0; i < 4; i++){
        int mt = wm*4 + i;
        uint4 ah = *(const uint4*)&S.Ah[mt][lane][0];
        uint4 al = *(const uint4*)&S.Al[mt][lane][0];
        #pragma unroll
        for (int j = 0; j < 4; j++){
            mma16(acc[i][j], ah, bh[j]);
            mma16(acc[i][j], ah, bl[j]);
            mma16(acc[i][j], al, bh[j]);
        }
    }
}

__device__ __forceinline__ void tcompC(const TSmemC &S, float (&acc)[8][4], int lane, int w)
{
    uint4 ah = *(const uint4*)&S.Ah[w][lane][0];
    uint4 al = *(const uint4*)&S.Al[w][lane][0];
    #pragma unroll
    for (int j = 0; j < 8; j++){
        uint2 bh = *(const uint2*)&S.Bh[j][lane][0];
        uint2 bl = *(const uint2*)&S.Bl[j][lane][0];
        mma16(acc[j], ah, bh);
        mma16(acc[j], ah, bl);
        mma16(acc[j], al, bh);
    }
}

// ---------------- prep ----------------
__global__ void k_prep(const float* __restrict__ W1, const float* __restrict__ W2,
                       const float* __restrict__ V,
                       const float* __restrict__ wih_f, const float* __restrict__ wih_b,
                       const float* __restrict__ bih_f, const float* __restrict__ bhh_f,
                       const float* __restrict__ bih_b, const float* __restrict__ bhh_b,
                       const float* __restrict__ c1w)
{
    int idx = blockIdx.x*blockDim.x + threadIdx.x;
    if (idx < 16384){ int n = idx/128, k = idx%128; g_W1T[k*128+n] = W1[idx]; }
    if (idx < 16384){ int n = idx/128, k = idx%128; g_W2T[k*128+n] = W2[idx]; }
    if (idx < 128*NTF_){ int n = idx/128, k = idx%128; g_VT[k*NTF_+n] = V[idx]; }
    if (idx < 16384){ int g = idx/64, k = idx%64;
        g_WIHT[k*512 + g]       = wih_f[idx];
        g_WIHT[k*512 + 256 + g] = wih_b[idx]; }
    if (idx < 512){ g_biasIH[idx] = (idx < 256) ? (bih_f[idx] + bhh_f[idx])
                                                : (bih_b[idx-256] + bhh_b[idx-256]); }
    if (idx < 32768){ int c = idx/512, k = idx%512; g_c1wT[k*64+c] = c1w[idx]; }
}

// ---------------- conv0 + bn + relu + maxpool4 ----------------
__global__ void __launch_bounds__(256) k_conv0(
    const float* __restrict__ x, const float* __restrict__ w, const float* __restrict__ cb,
    const float* __restrict__ g, const float* __restrict__ bb,
    const float* __restrict__ mm, const float* __restrict__ vv)
{
    __shared__ float4 xs4[1024];
    int b = blockIdx.x, tid = threadIdx.x;
    const float4* in4 = (const float4*)(x + (size_t)b*4096);
    for (int i = tid; i < 1024; i += 256) xs4[i] = in4[i];

    int c = tid & 63;
    float4 wr[8];
    #pragma unroll
    for (int kk = 0; kk < 8; kk++)
        wr[kk] = make_float4(w[c*32 + 0*8 + kk], w[c*32 + 1*8 + kk],
                             w[c*32 + 2*8 + kk], w[c*32 + 3*8 + kk]);
    float scale = g[c] * rsqrtf(vv[c] + 1e-5f);
    float shift = bb[c] - mm[c]*scale;
    float cbc   = cb[c];
    __syncthreads();

    for (int idx = tid; idx < 64*LPOOL; idx += 256){
        int q = idx >> 6;
        float best = -FLT_MAX;
        #pragma unroll
        for (int dp = 0; dp < 4; dp++){
            int p = 4*q + dp;
            float acc = cbc;
            #pragma unroll
            for (int kk = 0; kk < 8; kk++){
                float4 xv = xs4[p+kk];
                acc += wr[kk].x*xv.x + wr[kk].y*xv.y + wr[kk].z*xv.z + wr[kk].w*xv.w;
            }
            best = fmaxf(best, acc*scale + shift);
        }
        g_pooled[(b*64 + c)*LPOOL + q] = fmaxf(best, 0.f);
    }
}

// ---------------- conv1 GEMM (bf16 split MMA): M=126464, N=64, K=512 ----------------
__global__ void __launch_bounds__(256,2) k_conv1(
    const float* __restrict__ cb,
    const float* __restrict__ gg, const float* __restrict__ bb,
    const float* __restrict__ mm, const float* __restrict__ vv)
{
    __shared__ TSmemC S;
    int tid = threadIdx.x, lane = tid&31, w = tid>>5;
    int m0  = blockIdx.x*128;
    float acc[8][4];
    #pragma unroll
    for (int j=0;j<8;j++) for (int v=0;v<4;v++) acc[j][v]=0.f;

    int mA = tid>>3, kpA = tid&7;
    int bz[4], tl[4];
    #pragma unroll
    for (int r = 0; r < 4; r++){
        int gm = m0 + mA + 32*r;
        bz[r] = gm / T_;
        tl[r] = gm - bz[r]*T_;
    }

    float ax0[4], ax1[4], bx0[2], bx1[2];
    {
        int k = 2*kpA;
        #pragma unroll
        for (int r = 0; r < 4; r++){
            int base = (bz[r]*64 + (k>>3))*LPOOL + tl[r] + (k&7);
            ax0[r] = g_pooled[base]; ax1[r] = g_pooled[base+1];
        }
        #pragma unroll
        for (int r = 0; r < 2; r++){
            int i = tid + 256*r; int n = i&63, kp = (i>>6)&7;
            bx0[r] = g_c1wT[(2*kp)*64 + n];
            bx1[r] = g_c1wT[(2*kp+1)*64 + n];
        }
        #pragma unroll
        for (int r = 0; r < 4; r++) astoreB(S.Ah, S.Al, mA+32*r, kpA, ax0[r], ax1[r]);
        #pragma unroll
        for (int r = 0; r < 2; r++){
            int i = tid + 256*r; int n = i&63, kp = (i>>6)&7;
            bstoreB(&S.Bh[0][0][0], &S.Bl[0][0][0], kp, n, bx0[r], bx1[r]);
        }
    }
    __syncthreads();

    for (int c = 0; c < 32; c++){
        if (c < 31){
            int k0 = (c+1)*16;
            int k = k0 + 2*kpA;
            #pragma unroll
            for (int r = 0; r < 4; r++){
                int base = (bz[r]*64 + (k>>3))*LPOOL + tl[r] + (k&7);
                ax0[r] = g_pooled[base]; ax1[r] = g_pooled[base+1];
            }
            #pragma unroll
            for (int r = 0; r < 2; r++){
                int i = tid + 256*r; int n = i&63, kp = (i>>6)&7;
                bx0[r] = g_c1wT[(k0+2*kp)*64 + n];
                bx1[r] = g_c1wT[(k0+2*kp+1)*64 + n];
            }
        }
        tcompC(S, acc, lane, w);
        __syncthreads();
        if (c < 31){
            #pragma unroll
            for (int r = 0; r < 4; r++) astoreB(S.Ah, S.Al, mA+32*r, kpA, ax0[r], ax1[r]);
            #pragma unroll
            for (int r = 0; r < 2; r++){
                int i = tid + 256*r; int n = i&63, kp = (i>>6)&7;
                bstoreB(&S.Bh[0][0][0], &S.Bl[0][0][0], kp, n, bx0[r], bx1[r]);
            }
        }
        __syncthreads();
    }
    int g = lane>>2, tc = lane&3;
    #pragma unroll
    for (int j = 0; j < 8; j++){
        #pragma unroll
        for (int r2 = 0; r2 < 2; r2++){
            int row = m0 + w*16 + g + 8*r2;
            #pragma unroll
            for (int h = 0; h < 2; h++){
                int col = j*8 + tc*2 + h;
                float scale = gg[col] * rsqrtf(vv[col] + 1e-5f);
                float shift = bb[col] + (cb[col] - mm[col])*scale;
                float v = acc[j][r2*2+h];
                g_xlstm[(size_t)row*64 + col] = fmaxf(v*scale + shift, 0.f);
            }
        }
    }
}

// ---------------- xproj GEMM (bf16 split MMA): M=126464, N=512, K=64 ----------------
__global__ void __launch_bounds__(256,2) k_xproj()
{
    __shared__ TSmem S;
    int tid = threadIdx.x, lane = tid&31, w = tid>>5, wm = w>>2, wn = w&3;
    int n0 = blockIdx.x*128, m0 = blockIdx.y*128;
    float acc[4][4][4];
    #pragma unroll
    for (int i=0;i<4;i++) for (int j=0;j<4;j++) for (int v=0;v<4;v++) acc[i][j][v]=0.f;

    int mA = tid>>3, kpA = tid&7;
    int kpB = tid>>5, nB = tid&31;

    float2 ra[4]; float bx0[4], bx1[4];
    {
        #pragma unroll
        for (int r = 0; r < 4; r++)
            ra[r] = *(const float2*)&g_xlstm[(size_t)(m0+mA+32*r)*64 + 2*kpA];
        #pragma unroll
        for (int r = 0; r < 4; r++){
            int n = nB + 32*r;
            bx0[r] = g_WIHT[(2*kpB)*512 + n0 + n];
            bx1[r] = g_WIHT[(2*kpB+1)*512 + n0 + n];
        }
        #pragma unroll
        for (int r = 0; r < 4; r++) astoreB(S.Ah, S.Al, mA+32*r, kpA, ra[r].x, ra[r].y);
        #pragma unroll
        for (int r = 0; r < 4; r++)
            bstoreB(&S.Bh[0][0][0], &S.Bl[0][0][0], kpB, nB+32*r, bx0[r], bx1[r]);
    }
    __syncthreads();

    #pragma unroll
    for (int c = 0; c < 4; c++){
        if (c < 3){
            int k0 = (c+1)*16;
            #pragma unroll
            for (int r = 0; r < 4; r++)
                ra[r] = *(const float2*)&g_xlstm[(size_t)(m0+mA+32*r)*64 + k0 + 2*kpA];
            #pragma unroll
            for (int r = 0; r < 4; r++){
                int n = nB + 32*r;
                bx0[r] = g_WIHT[(k0+2*kpB)*512 + n0 + n];
                bx1[r] = g_WIHT[(k0+2*kpB+1)*512 + n0 + n];
            }
        }
        tcomp(S, acc, lane, wm, wn);
        __syncthreads();
        if (c < 3){
            #pragma unroll
            for (int r = 0; r < 4; r++) astoreB(S.Ah, S.Al, mA+32*r, kpA, ra[r].x, ra[r].y);
            #pragma unroll
            for (int r = 0; r < 4; r++)
                bstoreB(&S.Bh[0][0][0], &S.Bl[0][0][0], kpB, nB+32*r, bx0[r], bx1[r]);
        }
        __syncthreads();
    }
    int g = lane>>2, tc = lane&3;
    #pragma unroll
    for (int i=0;i<4;i++)
      #pragma unroll
      for (int j=0;j<4;j++)
        #pragma unroll
        for (int r2=0;r2<2;r2++){
            int row = m0 + wm*64 + i*16 + g + 8*r2;
            int col = n0 + wn*32 + j*8 + tc*2;
            float2 o = make_float2(acc[i][j][r2*2+0] + g_biasIH[col],
                                   acc[i][j][r2*2+1] + g_biasIH[col+1]);
            *(float2*)&g_xproj[(size_t)row*512 + col] = o;
        }
}

// ---------------- LSTM recurrence (persistent, f32x2, both dirs in one block) ----------------
__global__ void __launch_bounds__(512) k_lstm(const float* __restrict__ whh_f,
                                              const float* __restrict__ whh_b)
{
    __shared__ float hs[2][64][4];
    __shared__ float g_sm[2][4][256];
    int b0  = blockIdx.x * 4;
    int t512 = threadIdx.x;
    int dir = t512 >> 8;
    int tid = t512 & 255;
    const float* whh = dir ? whh_b : whh_f;

    float4 w4[16];
    #pragma unroll
    for (int j4 = 0; j4 < 16; j4++) w4[j4] = *(const float4*)&whh[tid*64 + j4*4];

    hs[dir][tid>>2][tid&3] = 0.f;
    float c = 0.f, hlast = 0.f;

    int tt0 = dir ? 246 : 0;
    float xv[4];
    #pragma unroll
    for (int bi = 0; bi < 4; bi++)
        xv[bi] = g_xproj[((size_t)(b0+bi)*T_ + tt0)*512 + dir*256 + tid];
    __syncthreads();

    for (int s = 0; s < T_; s++){
        u64 acc0 = pack2(xv[0], xv[1]);
        u64 acc1 = pack2(xv[2], xv[3]);

        float xn[4];
        if (s < T_-1){
            int tt2 = dir ? (245 - s) : (s + 1);
            #pragma unroll
            for (int bi = 0; bi < 4; bi++)
                xn[bi] = g_xproj[((size_t)(b0+bi)*T_ + tt2)*512 + dir*256 + tid];
        }

        #pragma unroll
        for (int j4 = 0; j4 < 16; j4++){
            float4 w = w4[j4];
            const ulonglong2* hq = (const ulonglong2*)&hs[dir][j4*4][0];
            ulonglong2 h0 = hq[0];
            ulonglong2 h1 = hq[1];
            ulonglong2 h2 = hq[2];
            ulonglong2 h3 = hq[3];
            u64 wx = pack2(w.x, w.x);
            u64 wy = pack2(w.y, w.y);
            u64 wz = pack2(w.z, w.z);
            u64 ww = pack2(w.w, w.w);
            acc0 = ffma2(wx, h0.x, acc0); acc1 = ffma2(wx, h0.y, acc1);
            acc0 = ffma2(wy, h1.x, acc0); acc1 = ffma2(wy, h1.y, acc1);
            acc0 = ffma2(wz, h2.x, acc0); acc1 = ffma2(wz, h2.y, acc1);
            acc0 = ffma2(ww, h3.x, acc0); acc1 = ffma2(ww, h3.y, acc1);
        }
        float2 f0 = unpack2(acc0), f1 = unpack2(acc1);
        g_sm[dir][0][tid] = f0.x; g_sm[dir][1][tid] = f0.y;
        g_sm[dir][2][tid] = f1.x; g_sm[dir][3][tid] = f1.y;
        __syncthreads();

        int tv = dir ? (246 - s) : s;
        {
            int bi = tid >> 6, j = tid & 63;
            float gi = sigf(g_sm[dir][bi][j]);
            float gf = sigf(g_sm[dir][bi][64+j]);
            float gc = tanhf(g_sm[dir][bi][128+j]);
            float go = sigf(g_sm[dir][bi][192+j]);
            c = gf*c + gi*gc;
            float h = go * tanhf(c);
            hlast = h;
            hs[dir][j][bi] = h;
            g_values[((size_t)(b0+bi)*T_ + tv)*128 + dir*64 + j] = h;
        }
        __syncthreads();
        #pragma unroll
        for (int bi = 0; bi < 4; bi++) xv[bi] = xn[bi];
    }
    {
        int bi = tid >> 6, j = tid & 63;
        g_hT[dir*B_*64 + (b0+bi)*64 + j] = hlast;
    }
}

// ---------------- h_n build + query ----------------
__global__ void k_hnquery(const float* __restrict__ W2b)
{
    __shared__ float hn[128];
    int b = blockIdx.x, j = threadIdx.x;
    int half = j >> 6, jj = j & 63;
    float v;
    if (b < 256) v = g_hT[(2*b + half)*64 + jj];
    else         v = g_hT[B_*64 + (2*(b-256) + half)*64 + jj];
    hn[j] = v;
    __syncthreads();
    float acc = W2b[j];
    #pragma unroll 4
    for (int k = 0; k < 128; k++) acc += hn[k] * g_W2T[k*128 + j];
    g_query[b*128 + j] = acc;
}

// ---------------- keys GEMM + tanh (bf16 split MMA): M=126464, N=128, K=128 ----------------
__global__ void __launch_bounds__(256,2) k_keys(const float* __restrict__ W1b)
{
    __shared__ TSmem S;
    int tid = threadIdx.x, lane = tid&31, w = tid>>5, wm = w>>2, wn = w&3;
    int m0 = blockIdx.x*128;
    float acc[4][4][4];
    #pragma unroll
    for (int i=0;i<4;i++) for (int j=0;j<4;j++) for (int v=0;v<4;v++) acc[i][j][v]=0.f;

    int mA = tid>>3, kpA = tid&7;
    int kpB = tid>>5, nB = tid&31;

    float2 ra[4]; float bx0[4], bx1[4];
    {
        #pragma unroll
        for (int r = 0; r < 4; r++)
            ra[r] = *(const float2*)&g_values[(size_t)(m0+mA+32*r)*128 + 2*kpA];
        #pragma unroll
        for (int r = 0; r < 4; r++){
            int n = nB + 32*r;
            bx0[r] = g_W1T[(2*kpB)*128 + n];
            bx1[r] = g_W1T[(2*kpB+1)*128 + n];
        }
        #pragma unroll
        for (int r = 0; r < 4; r++) astoreB(S.Ah, S.Al, mA+32*r, kpA, ra[r].x, ra[r].y);
        #pragma unroll
        for (int r = 0; r < 4; r++)
            bstoreB(&S.Bh[0][0][0], &S.Bl[0][0][0], kpB, nB+32*r, bx0[r], bx1[r]);
    }
    __syncthreads();

    #pragma unroll
    for (int c = 0; c < 8; c++){
        if (c < 7){
            int k0 = (c+1)*16;
            #pragma unroll
            for (int r = 0; r < 4; r++)
                ra[r] = *(const float2*)&g_values[(size_t)(m0+mA+32*r)*128 + k0 + 2*kpA];
            #pragma unroll
            for (int r = 0; r < 4; r++){
                int n = nB + 32*r;
                bx0[r] = g_W1T[(k0+2*kpB)*128 + n];
                bx1[r] = g_W1T[(k0+2*kpB+1)*128 + n];
            }
        }
        tcomp(S, acc, lane, wm, wn);
        __syncthreads();
        if (c < 7){
            #pragma unroll
            for (int r = 0; r < 4; r++) astoreB(S.Ah, S.Al, mA+32*r, kpA, ra[r].x, ra[r].y);
            #pragma unroll
            for (int r = 0; r < 4; r++)
                bstoreB(&S.Bh[0][0][0], &S.Bl[0][0][0], kpB, nB+32*r, bx0[r], bx1[r]);
        }
        __syncthreads();
    }
    int g = lane>>2, tc = lane&3;
    #pragma unroll
    for (int i=0;i<4;i++)
      #pragma unroll
      for (int j=0;j<4;j++)
        #pragma unroll
        for (int r2=0;r2<2;r2++){
            int row = m0 + wm*64 + i*16 + g + 8*r2;
            int b = row / T_;
            int col = wn*32 + j*8 + tc*2;
            float e0 = tanhf(acc[i][j][r2*2+0] + W1b[col]   + g_query[b*128 + col]);
            float e1 = tanhf(acc[i][j][r2*2+1] + W1b[col+1] + g_query[b*128 + col+1]);
            *(float2*)&g_E[(size_t)row*128 + col] = make_float2(e0, e1);
        }
}

// ---------------- score GEMM (bf16 split MMA, batched): per b, M=247, N=200, K=128 ----------------
__global__ void __launch_bounds__(256,2) k_scoreK(const float* __restrict__ Vb)
{
    __shared__ TSmem S;
    int tid = threadIdx.x, lane = tid&31, w = tid>>5, wm = w>>2, wn = w&3;
    int n0 = blockIdx.x*128, m0 = blockIdx.y*128, b = blockIdx.z;
    float acc[4][4][4];
    #pragma unroll
    for (int i=0;i<4;i++) for (int j=0;j<4;j++) for (int v=0;v<4;v++) acc[i][j][v]=0.f;

    int mA = tid>>3, kpA = tid&7;
    int kpB = tid>>5, nB = tid&31;

    float2 ra[4]; float bx0[4], bx1[4];
    {
        #pragma unroll
        for (int r = 0; r < 4; r++){
            int m = mA + 32*r;
            ra[r] = (m0+m < T_) ? *(const float2*)&g_E[((size_t)b*T_ + m0+m)*128 + 2*kpA]
                                : make_float2(0.f, 0.f);
        }
        #pragma unroll
        for (int r = 0; r < 4; r++){
            int n = nB + 32*r;
            bool ok = (n0+n < NTF_);
            bx0[r] = ok ? g_VT[(2*kpB)*NTF_ + n0+n] : 0.f;
            bx1[r] = ok ? g_VT[(2*kpB+1)*NTF_ + n0+n] : 0.f;
        }
        #pragma unroll
        for (int r = 0; r < 4; r++) astoreB(S.Ah, S.Al, mA+32*r, kpA, ra[r].x, ra[r].y);
        #pragma unroll
        for (int r = 0; r < 4; r++)
            bstoreB(&S.Bh[0][0][0], &S.Bl[0][0][0], kpB, nB+32*r, bx0[r], bx1[r]);
    }
    __syncthreads();

    #pragma unroll
    for (int c = 0; c < 8; c++){
        if (c < 7){
            int k0 = (c+1)*16;
            #pragma unroll
            for (int r = 0; r < 4; r++){
                int m = mA + 32*r;
                ra[r] = (m0+m < T_) ? *(const float2*)&g_E[((size_t)b*T_ + m0+m)*128 + k0 + 2*kpA]
                                    : make_float2(0.f, 0.f);
            }
            #pragma unroll
            for (int r = 0; r < 4; r++){
                int n = nB + 32*r;
                bool ok = (n0+n < NTF_);
                bx0[r] = ok ? g_VT[(k0+2*kpB)*NTF_ + n0+n] : 0.f;
                bx1[r] = ok ? g_VT[(k0+2*kpB+1)*NTF_ + n0+n] : 0.f;
            }
        }
        tcomp(S, acc, lane, wm, wn);
        __syncthreads();
        if (c < 7){
            #pragma unroll
            for (int r = 0; r < 4; r++) astoreB(S.Ah, S.Al, mA+32*r, kpA, ra[r].x, ra[r].y);
            #pragma unroll
            for (int r = 0; r < 4; r++)
                bstoreB(&S.Bh[0][0][0], &S.Bl[0][0][0], kpB, nB+32*r, bx0[r], bx1[r]);
        }
        __syncthreads();
    }
    int g = lane>>2, tc = lane&3;
    #pragma unroll
    for (int i=0;i<4;i++)
      #pragma unroll
      for (int j=0;j<4;j++)
        #pragma unroll
        for (int r2=0;r2<2;r2++){
            int row = m0 + wm*64 + i*16 + g + 8*r2;
            int col = n0 + wn*32 + j*8 + tc*2;
            if (row < T_ && col < NTF_){
                float2 o = make_float2(acc[i][j][r2*2+0] + Vb[col],
                                       acc[i][j][r2*2+1] + Vb[col+1]);
                *(float2*)&g_score[((size_t)b*T_ + row)*NTF_ + col] = o;
            }
        }
}

// ---------------- softmax over time ----------------
__global__ void k_softmax()
{
    int b = blockIdx.x, k = threadIdx.x;
    if (k >= NTF_) return;
    float* base = g_score + (size_t)b*T_*NTF_ + k;
    float m = -FLT_MAX, s = 0.f;
    for (int t = 0; t < T_; t++){
        float x = base[t*NTF_];
        if (x > m){ s = s*__expf(m - x) + 1.f; m = x; }
        else s += __expf(x - m);
    }
    float inv = 1.f / s;
    for (int t = 0; t < T_; t++){
        float x = base[t*NTF_];
        base[t*NTF_] = __expf(x - m) * inv;
    }
}

// ---------------- context GEMM (bf16 split MMA, batched): per b, M=200, N=128, K=247 ----------------
__global__ void __launch_bounds__(256,2) k_context()
{
    __shared__ TSmem S;
    int tid = threadIdx.x, lane = tid&31, w = tid>>5, wm = w>>2, wn = w&3;
    int m0 = blockIdx.x*128, b = blockIdx.y;
    float acc[4][4][4];
    #pragma unroll
    for (int i=0;i<4;i++) for (int j=0;j<4;j++) for (int v=0;v<4;v++) acc[i][j][v]=0.f;

    int kpB = tid>>5, mB = tid&31;

    float ax0[4], ax1[4], bx0[4], bx1[4];
    {
        #pragma unroll
        for (int r = 0; r < 4; r++){
            int m = mB + 32*r;
            bool okm = (m0+m < NTF_);
            int t0 = 2*kpB, t1 = 2*kpB+1;
            ax0[r] = (okm && t0 < T_) ? g_score[((size_t)b*T_ + t0)*NTF_ + m0+m] : 0.f;
            ax1[r] = (okm && t1 < T_) ? g_score[((size_t)b*T_ + t1)*NTF_ + m0+m] : 0.f;
            bx0[r] = (t0 < T_) ? g_values[((size_t)b*T_ + t0)*128 + m] : 0.f;
            bx1[r] = (t1 < T_) ? g_values[((size_t)b*T_ + t1)*128 + m] : 0.f;
        }
        #pragma unroll
        for (int r = 0; r < 4; r++){
            astoreB(S.Ah, S.Al, mB+32*r, kpB, ax0[r], ax1[r]);
            bstoreB(&S.Bh[0][0][0], &S.Bl[0][0][0], kpB, mB+32*r, bx0[r], bx1[r]);
        }
    }
    __syncthreads();

    for (int c = 0; c < 16; c++){
        if (c < 15){
            int k0 = (c+1)*16;
            #pragma unroll
            for (int r = 0; r < 4; r++){
                int m = mB + 32*r;
                bool okm = (m0+m < NTF_);
                int t0 = k0 + 2*kpB, t1 = t0 + 1;
                ax0[r] = (okm && t0 < T_) ? g_score[((size_t)b*T_ + t0)*NTF_ + m0+m] : 0.f;
                ax1[r] = (okm && t1 < T_) ? g_score[((size_t)b*T_ + t1)*NTF_ + m0+m] : 0.f;
                bx0[r] = (t0 < T_) ? g_values[((size_t)b*T_ + t0)*128 + m] : 0.f;
                bx1[r] = (t1 < T_) ? g_values[((size_t)b*T_ + t1)*128 + m] : 0.f;
            }
        }
        tcomp(S, acc, lane, wm, wn);
        __syncthreads();
        if (c < 15){
            #pragma unroll
            for (int r = 0; r < 4; r++){
                astoreB(S.Ah, S.Al, mB+32*r, kpB, ax0[r], ax1[r]);
                bstoreB(&S.Bh[0][0][0], &S.Bl[0][0][0], kpB, mB+32*r, bx0[r], bx1[r]);
            }
        }
        __syncthreads();
    }
    int g = lane>>2, tc = lane&3;
    #pragma unroll
    for (int i=0;i<4;i++)
      #pragma unroll
      for (int j=0;j<4;j++)
        #pragma unroll
        for (int r2=0;r2<2;r2++){
            int row = m0 + wm*64 + i*16 + g + 8*r2;
            int col = wn*32 + j*8 + tc*2;
            if (row < NTF_){
                float2 o = make_float2(acc[i][j][r2*2+0], acc[i][j][r2*2+1]);
                *(float2*)&g_ctx[((size_t)b*NTF_ + row)*128 + col] = o;
            }
        }
}

// ---------------- per-TF heads ----------------
__global__ void __launch_bounds__(256) k_heads(
    const float* __restrict__ fc1w, const float* __restrict__ fc1b,
    const float* __restrict__ fc2w, const float* __restrict__ fc2b,
    float* __restrict__ out)
{
    __shared__ float fw[128][65];
    __shared__ float cs[16][128];
    __shared__ float red[16][65];
    int tid = threadIdx.x;
    int b0 = blockIdx.x*16, k = blockIdx.y;

    for (int i = tid; i < 8192; i += 256){
        int o = i >> 7, d = i & 127;
        fw[d][o] = fc1w[(size_t)k*8192 + i];
    }
    for (int i = tid; i < 2048; i += 256){
        int bi = i >> 7, d = i & 127;
        cs[bi][d] = g_ctx[((size_t)(b0+bi)*NTF_ + k)*128 + d];
    }
    __syncthreads();

    int o = tid & 63;
    float f1b = fc1b[k*64 + o];
    float f2w = fc2w[k*64 + o];
    #pragma unroll
    for (int p = 0; p < 4; p++){
        int bi = (tid >> 6) + p*4;
        float acc = 0.f;
        #pragma unroll
        for (int d4 = 0; d4 < 32; d4++){
            float4 cv = *(const float4*)&cs[bi][d4*4];
            acc += fw[d4*4+0][o]*cv.x + fw[d4*4+1][o]*cv.y
                 + fw[d4*4+2][o]*cv.z + fw[d4*4+3][o]*cv.w;
        }
        float h1 = fmaxf(acc + f1b, 0.f);
        red[bi][o] = h1 * f2w;
    }
    __syncthreads();
    if (tid < 16){
        float s = fc2b[k];
        #pragma unroll 8
        for (int oo = 0; oo < 64; oo++) s += red[tid][oo];
        out[(size_t)(b0 + tid)*NTF_ + k] = s;
    }
}

// ---------------- launch ----------------
extern "C" void kernel_launch(void* const* d_in, const int* in_sizes, int n_in,
                              void* d_out, int out_size)
{
    const float* DNA    = (const float*)d_in[0];
    const float* c0w    = (const float*)d_in[1];
    const float* c0b    = (const float*)d_in[2];
    const float* bn0g   = (const float*)d_in[3];
    const float* bn0b   = (const float*)d_in[4];
    const float* bn0m   = (const float*)d_in[5];
    const float* bn0v   = (const float*)d_in[6];
    const float* c1w    = (const float*)d_in[7];
    const float* c1b    = (const float*)d_in[8];
    const float* bn1g   = (const float*)d_in[9];
    const float* bn1b   = (const float*)d_in[10];
    const float* bn1m   = (const float*)d_in[11];
    const float* bn1v   = (const float*)d_in[12];
    const float* wih_f  = (const float*)d_in[13];
    const float* whh_f  = (const float*)d_in[14];
    const float* bih_f  = (const float*)d_in[15];
    const float* bhh_f  = (const float*)d_in[16];
    const float* wih_b  = (const float*)d_in[17];
    const float* whh_b  = (const float*)d_in[18];
    const float* bih_b  = (const float*)d_in[19];
    const float* bhh_b  = (const float*)d_in[20];
    const float* W1w    = (const float*)d_in[21];
    const float* W1b    = (const float*)d_in[22];
    const float* W2w    = (const float*)d_in[23];
    const float* W2b    = (const float*)d_in[24];
    const float* Vw     = (const float*)d_in[25];
    const float* Vb     = (const float*)d_in[26];
    const float* fc1w   = (const float*)d_in[27];
    const float* fc1b   = (const float*)d_in[28];
    const float* fc2w   = (const float*)d_in[29];
    const float* fc2b   = (const float*)d_in[30];
    float* out = (float*)d_out;

    k_prep<<<512, 256>>>(W1w, W2w, Vw, wih_f, wih_b, bih_f, bhh_f, bih_b, bhh_b, c1w);
    k_conv0<<<512, 256>>>(DNA, c0w, c0b, bn0g, bn0b, bn0m, bn0v);
    k_conv1<<<988, 256>>>(c1b, bn1g, bn1b, bn1m, bn1v);
    k_xproj<<<dim3(4, 988), 256>>>();
    k_lstm<<<128, 512>>>(whh_f, whh_b);
    k_hnquery<<<512, 128>>>(W2b);
    k_keys<<<988, 256>>>(W1b);
    k_scoreK<<<dim3(2, 2, 512), 256>>>(Vb);
    k_softmax<<<512, 256>>>();
    k_context<<<dim3(2, 512), 256>>>();
    k_heads<<<dim3(32, 200), 256>>>(fc1w, fc1b, fc2w, fc2b, out);
}